// round 1
// baseline (speedup 1.0000x reference)
#include <cuda_runtime.h>
#include <math.h>

#define NH   8
#define HD   24
#define CDIM 192
#define NTOK 64
#define HW   65536   // 256*256
#define NB   4
#define KDIM 192

// ---------------- device scratch (static; no allocations allowed) ----------------
__device__ float g_qkv[(size_t)NB * 3 * CDIM * HW];   // (B, 576, 65536)
__device__ float g_att[(size_t)NB * CDIM * HW];       // (B, 192, 65536)
__device__ float g_bias[NH * NTOK * NTOK];            // (8, 64, 64)
__device__ float g_qkvb[3 * CDIM];                    // concat [q_bias, 0, v_bias]

// ---------------- kernel 1: CPB bias table + qkv bias vector ----------------
__global__ void bias_kernel(const float* __restrict__ w1, const float* __restrict__ b1,
                            const float* __restrict__ w2,
                            const float* __restrict__ qb, const float* __restrict__ vb)
{
    __shared__ float table[225][NH];
    int tid = threadIdx.x;

    // qkv bias vector
    for (int i = tid; i < 3 * CDIM; i += blockDim.x) {
        float v = 0.f;
        if (i < CDIM)            v = qb[i];
        else if (i >= 2 * CDIM)  v = vb[i - 2 * CDIM];
        g_qkvb[i] = v;
    }

    // CPB MLP: table[r][h] = relu(RCT[r] @ w1 + b1) @ w2
    if (tid < 225) {
        int a = tid / 15, b = tid % 15;
        const float inv_l8 = 1.0f / log2f(8.0f);
        float ca = (float)(a - 7) / 7.0f * 8.0f;
        float cb = (float)(b - 7) / 7.0f * 8.0f;
        float r0 = (ca == 0.f) ? 0.f : copysignf(log2f(fabsf(ca) + 1.0f) * inv_l8, ca);
        float r1 = (cb == 0.f) ? 0.f : copysignf(log2f(fabsf(cb) + 1.0f) * inv_l8, cb);
        float acc[NH];
        #pragma unroll
        for (int h = 0; h < NH; h++) acc[h] = 0.f;
        for (int j = 0; j < 512; j++) {
            float hv = fmaf(r0, w1[j], fmaf(r1, w1[512 + j], b1[j]));
            hv = fmaxf(hv, 0.f);
            #pragma unroll
            for (int h = 0; h < NH; h++) acc[h] = fmaf(hv, w2[j * NH + h], acc[h]);
        }
        #pragma unroll
        for (int h = 0; h < NH; h++) table[tid][h] = acc[h];
    }
    __syncthreads();

    // g_bias[h][n][m] = 16*sigmoid(table[rpi(n,m)][h])
    for (int idx = tid; idx < NH * NTOK * NTOK; idx += blockDim.x) {
        int h  = idx / (NTOK * NTOK);
        int nm = idx % (NTOK * NTOK);
        int n = nm / NTOK, m = nm % NTOK;
        int di = (n >> 3) - (m >> 3) + 7;
        int dj = (n & 7) - (m & 7) + 7;
        float t = table[di * 15 + dj][h];
        g_bias[idx] = 16.f / (1.f + expf(-t));
    }
}

// ---------------- kernel 2/4: fp32 SGEMM, C[M,HW] = W[M,192] @ X[192,HW] + bias (+resid) ----------------
// BM=64 BN=128 BK=16, 256 threads, 4x8 per-thread tile
template<bool RES>
__global__ void __launch_bounds__(256) gemm192(
    const float* __restrict__ Wm,     // M x 192 row-major
    const float* __restrict__ bias,   // M
    const float* __restrict__ X,      // per batch: 192 x HW
    const float* __restrict__ resid,  // per batch: 192 x HW (only if RES)
    float* __restrict__ out,          // per batch: M x HW
    int M)
{
    __shared__ float As[16][64];
    __shared__ float Bs[16][128];

    const int bz = blockIdx.z;
    const int m0 = blockIdx.y * 64;
    const int n0 = blockIdx.x * 128;
    const float* Xb = X + (size_t)bz * KDIM * HW + n0;
    float* Ob = out + (size_t)bz * M * HW;

    const int tid = threadIdx.x;
    const int tm = tid >> 4;     // 0..15 -> rows tm*4
    const int tn = tid & 15;     // 0..15 -> cols tn*8

    float acc[4][8];
    #pragma unroll
    for (int i = 0; i < 4; i++)
        #pragma unroll
        for (int j = 0; j < 8; j++) acc[i][j] = 0.f;

    for (int k0 = 0; k0 < KDIM; k0 += 16) {
        // A tile: W[m0+m][k0+k] -> As[k][m]
        {
            int m  = tid >> 2;
            int kq = (tid & 3) * 4;
            float4 a = *(const float4*)&Wm[(size_t)(m0 + m) * KDIM + k0 + kq];
            As[kq + 0][m] = a.x; As[kq + 1][m] = a.y;
            As[kq + 2][m] = a.z; As[kq + 3][m] = a.w;
        }
        // B tile: X[k0+k][n0+n]
        #pragma unroll
        for (int r = 0; r < 2; r++) {
            int idx = tid + r * 256;
            int kk = idx >> 5;
            int nq = (idx & 31) * 4;
            *(float4*)&Bs[kk][nq] = *(const float4*)&Xb[(size_t)(k0 + kk) * HW + nq];
        }
        __syncthreads();
        #pragma unroll
        for (int kk = 0; kk < 16; kk++) {
            float a[4], b[8];
            *(float4*)a       = *(const float4*)&As[kk][tm * 4];
            *(float4*)b       = *(const float4*)&Bs[kk][tn * 8];
            *(float4*)(b + 4) = *(const float4*)&Bs[kk][tn * 8 + 4];
            #pragma unroll
            for (int i = 0; i < 4; i++)
                #pragma unroll
                for (int j = 0; j < 8; j++)
                    acc[i][j] = fmaf(a[i], b[j], acc[i][j]);
        }
        __syncthreads();
    }

    #pragma unroll
    for (int i = 0; i < 4; i++) {
        int m = m0 + tm * 4 + i;
        float bv = bias[m];
        size_t row = (size_t)m * HW + n0 + tn * 8;
        #pragma unroll
        for (int j = 0; j < 8; j += 4) {
            float4 o;
            o.x = acc[i][j + 0] + bv; o.y = acc[i][j + 1] + bv;
            o.z = acc[i][j + 2] + bv; o.w = acc[i][j + 3] + bv;
            if (RES) {
                float4 rv = *(const float4*)&resid[(size_t)bz * CDIM * HW + row + j];
                o.x += rv.x; o.y += rv.y; o.z += rv.z; o.w += rv.w;
            }
            *(float4*)&Ob[row + j] = o;
        }
    }
}

// ---------------- kernel 3: per-window cosine attention ----------------
// one block per window (grid 1024 x 4), 256 threads, head loop inside
__global__ void __launch_bounds__(256) attn_kernel(const float* __restrict__ logit_scale)
{
    __shared__ float q[64][25], k[64][25], v[64][25];
    __shared__ float S[64][65];

    const int bz  = blockIdx.y;
    const int wid = blockIdx.x;
    const int wy = wid >> 5, wx = wid & 31;
    const int tid = threadIdx.x;

    const size_t qkvbase = (size_t)bz * (3 * CDIM) * HW;
    const size_t obase0  = (size_t)bz * CDIM * HW;
    const float LN100 = 4.6051701860f;

    for (int h = 0; h < NH; h++) {
        const float scale_h = expf(fminf(logit_scale[h], LN100));

        // gather q,k,v (64 x 24 each) for this head
        for (int idx = tid; idx < 3 * 64 * HD; idx += 256) {
            int which = idx / (64 * HD);
            int rem   = idx % (64 * HD);
            int d = rem / 64, t = rem % 64;
            int sp = (wy * 8 + (t >> 3)) * 256 + wx * 8 + (t & 7);
            int ch = which * CDIM + h * HD + d;
            float val = g_qkv[qkvbase + (size_t)ch * HW + sp];
            float (*dst)[25] = (which == 0) ? q : (which == 1) ? k : v;
            dst[t][d] = val;
        }
        __syncthreads();

        // cosine-normalize rows; fold head scale into q
        if (tid < 128) {
            int t = tid & 63;
            float* row = (tid < 64) ? q[t] : k[t];
            float ss = 0.f;
            #pragma unroll
            for (int d = 0; d < HD; d++) ss = fmaf(row[d], row[d], ss);
            float inv = 1.f / fmaxf(sqrtf(ss), 1e-12f);
            if (tid < 64) inv *= scale_h;
            #pragma unroll
            for (int d = 0; d < HD; d++) row[d] *= inv;
        }
        __syncthreads();

        // S[n][m] = qn . kn + bias
        {
            int n  = tid >> 2;
            int mq = (tid & 3) * 16;
            float qr[HD];
            #pragma unroll
            for (int d = 0; d < HD; d++) qr[d] = q[n][d];
            #pragma unroll 4
            for (int mm = 0; mm < 16; mm++) {
                int m = mq + mm;
                float a = 0.f;
                #pragma unroll
                for (int d = 0; d < HD; d++) a = fmaf(qr[d], k[m][d], a);
                S[n][m] = a + g_bias[(h * 64 + n) * 64 + m];
            }
        }
        __syncthreads();

        // softmax per row, 4 threads/row via quad shuffles
        {
            int n  = tid >> 2;
            int mq = (tid & 3) * 16;
            float mx = -1e30f;
            #pragma unroll
            for (int mm = 0; mm < 16; mm++) mx = fmaxf(mx, S[n][mq + mm]);
            mx = fmaxf(mx, __shfl_xor_sync(0xffffffffu, mx, 1));
            mx = fmaxf(mx, __shfl_xor_sync(0xffffffffu, mx, 2));
            float sum = 0.f;
            #pragma unroll
            for (int mm = 0; mm < 16; mm++) {
                float e = expf(S[n][mq + mm] - mx);
                S[n][mq + mm] = e;
                sum += e;
            }
            sum += __shfl_xor_sync(0xffffffffu, sum, 1);
            sum += __shfl_xor_sync(0xffffffffu, sum, 2);
            float inv = 1.f / sum;
            #pragma unroll
            for (int mm = 0; mm < 16; mm++) S[n][mq + mm] *= inv;
        }
        __syncthreads();

        // O = P @ v  -> write straight to g_att channels [h*24 .. h*24+23]
        {
            int n  = tid >> 2;
            int dq = (tid & 3) * 6;
            float acc[6] = {0.f, 0.f, 0.f, 0.f, 0.f, 0.f};
            #pragma unroll 8
            for (int m = 0; m < 64; m++) {
                float p = S[n][m];
                #pragma unroll
                for (int j = 0; j < 6; j++) acc[j] = fmaf(p, v[m][dq + j], acc[j]);
            }
            int sp = (wy * 8 + (n >> 3)) * 256 + wx * 8 + (n & 7);
            #pragma unroll
            for (int j = 0; j < 6; j++)
                g_att[obase0 + (size_t)(h * HD + dq + j) * HW + sp] = acc[j];
        }
        __syncthreads();
    }
}

// ---------------- launch ----------------
extern "C" void kernel_launch(void* const* d_in, const int* in_sizes, int n_in,
                              void* d_out, int out_size)
{
    const float* x        = (const float*)d_in[0];
    // d_in[1] = img_alpha (unused, no-op in reference)
    const float* qkv_w    = (const float*)d_in[2];
    const float* q_bias   = (const float*)d_in[3];
    const float* v_bias   = (const float*)d_in[4];
    const float* lscale   = (const float*)d_in[5];
    const float* cpb_w1   = (const float*)d_in[6];
    const float* cpb_b1   = (const float*)d_in[7];
    const float* cpb_w2   = (const float*)d_in[8];
    const float* proj_w   = (const float*)d_in[9];
    const float* proj_b   = (const float*)d_in[10];
    float* out = (float*)d_out;

    float* qkv_buf; cudaGetSymbolAddress((void**)&qkv_buf, g_qkv);
    float* att_buf; cudaGetSymbolAddress((void**)&att_buf, g_att);
    float* qkvb;    cudaGetSymbolAddress((void**)&qkvb,    g_qkvb);

    bias_kernel<<<1, 256>>>(cpb_w1, cpb_b1, cpb_w2, q_bias, v_bias);

    // QKV: (576,192) @ (192,65536) per batch
    gemm192<false><<<dim3(HW / 128, (3 * CDIM) / 64, NB), 256>>>(
        qkv_w, qkvb, x, nullptr, qkv_buf, 3 * CDIM);

    // windowed cosine attention
    attn_kernel<<<dim3(1024, NB), 256>>>(lscale);

    // proj + bias + residual -> output
    gemm192<true><<<dim3(HW / 128, CDIM / 64, NB), 256>>>(
        proj_w, proj_b, att_buf, x, out, CDIM);
}

// round 3
// speedup vs baseline: 1.9883x; 1.9883x over previous
#include <cuda_runtime.h>
#include <math.h>

#define NH   8
#define HD   24
#define CDIM 192
#define NTOK 64
#define HW   65536   // 256*256
#define NB   4
#define KDIM 192

// ---------------- device scratch ----------------
__device__ float g_qkv[(size_t)NB * 3 * CDIM * HW];   // (B, 576, 65536)
__device__ float g_att[(size_t)NB * CDIM * HW];       // (B, 192, 65536)
__device__ float g_bias[NH * NTOK * NTOK];            // (8, 64, 64)
__device__ float g_qkvb[3 * CDIM];                    // concat [q_bias, 0, v_bias]

// ---------------- kernel 1: CPB bias table + qkv bias vector ----------------
__global__ void bias_kernel(const float* __restrict__ w1, const float* __restrict__ b1,
                            const float* __restrict__ w2,
                            const float* __restrict__ qb, const float* __restrict__ vb)
{
    __shared__ float table[225][NH];
    int tid = threadIdx.x;

    for (int i = tid; i < 3 * CDIM; i += blockDim.x) {
        float v = 0.f;
        if (i < CDIM)            v = qb[i];
        else if (i >= 2 * CDIM)  v = vb[i - 2 * CDIM];
        g_qkvb[i] = v;
    }

    if (tid < 225) {
        int a = tid / 15, b = tid % 15;
        const float inv_l8 = 1.0f / log2f(8.0f);
        float ca = (float)(a - 7) / 7.0f * 8.0f;
        float cb = (float)(b - 7) / 7.0f * 8.0f;
        float r0 = (ca == 0.f) ? 0.f : copysignf(log2f(fabsf(ca) + 1.0f) * inv_l8, ca);
        float r1 = (cb == 0.f) ? 0.f : copysignf(log2f(fabsf(cb) + 1.0f) * inv_l8, cb);
        float acc[NH];
        #pragma unroll
        for (int h = 0; h < NH; h++) acc[h] = 0.f;
        for (int j = 0; j < 512; j++) {
            float hv = fmaf(r0, w1[j], fmaf(r1, w1[512 + j], b1[j]));
            hv = fmaxf(hv, 0.f);
            #pragma unroll
            for (int h = 0; h < NH; h++) acc[h] = fmaf(hv, w2[j * NH + h], acc[h]);
        }
        #pragma unroll
        for (int h = 0; h < NH; h++) table[tid][h] = acc[h];
    }
    __syncthreads();

    for (int idx = tid; idx < NH * NTOK * NTOK; idx += blockDim.x) {
        int h  = idx / (NTOK * NTOK);
        int nm = idx % (NTOK * NTOK);
        int n = nm / NTOK, m = nm % NTOK;
        int di = (n >> 3) - (m >> 3) + 7;
        int dj = (n & 7) - (m & 7) + 7;
        float t = table[di * 15 + dj][h];
        g_bias[idx] = 16.f / (1.f + expf(-t));
    }
}

// ---------------- kernel 2/4: SGEMM  C[M,HW] = W[M,192] @ X[192,HW] (+bias, +resid) ----------------
// BM=64 BN=256 BK=8, 256 threads, 8x8 per-thread tile, register-prefetch pipeline
template<bool RES>
__global__ void __launch_bounds__(256) gemm2(
    const float* __restrict__ Wm,     // M x 192 row-major
    const float* __restrict__ bias,   // M
    const float* __restrict__ X,      // per batch: 192 x HW
    const float* __restrict__ resid,  // per batch: 192 x HW (only if RES)
    float* __restrict__ out,          // per batch: M x HW
    int M)
{
    __shared__ float As[8][64];
    __shared__ float Bs[8][256];

    const int bz = blockIdx.z;
    const int m0 = blockIdx.y * 64;
    const int n0 = blockIdx.x * 256;
    const float* Xb = X + (size_t)bz * KDIM * HW + n0;
    float* Ob = out + (size_t)bz * M * HW;

    const int tid = threadIdx.x;
    const int tm = tid >> 5;     // 0..7  -> rows tm*8 .. tm*8+7
    const int tn = tid & 31;     // 0..31 -> cols tn*4 and 128+tn*4

    // loader indices
    const int am = tid >> 2;            // 0..63  A row
    const int ak = (tid & 3) * 2;       // 0,2,4,6 A k-pair
    const int bk = tid >> 5;            // 0..7   B k row
    const int bn = (tid & 31) * 4;      // B col (first 128), +128 for second

    const float* Aptr = Wm + (size_t)(m0 + am) * KDIM + ak;
    const float* Bptr = Xb + (size_t)bk * HW + bn;

    float acc[8][8];
    #pragma unroll
    for (int i = 0; i < 8; i++)
        #pragma unroll
        for (int j = 0; j < 8; j++) acc[i][j] = 0.f;

    float2 ar = *(const float2*)Aptr;
    float4 br0 = *(const float4*)Bptr;
    float4 br1 = *(const float4*)(Bptr + 128);

    for (int k0 = 0; k0 < KDIM; k0 += 8) {
        __syncthreads();
        As[ak][am] = ar.x;
        As[ak + 1][am] = ar.y;
        *(float4*)&Bs[bk][bn]       = br0;
        *(float4*)&Bs[bk][bn + 128] = br1;
        __syncthreads();

        if (k0 + 8 < KDIM) {
            ar  = *(const float2*)(Aptr + k0 + 8);
            const float* bp = Bptr + (size_t)(k0 + 8) * HW;
            br0 = *(const float4*)bp;
            br1 = *(const float4*)(bp + 128);
        }

        #pragma unroll
        for (int kk = 0; kk < 8; kk++) {
            float a[8], b[8];
            *(float4*)(a)     = *(const float4*)&As[kk][tm * 8];
            *(float4*)(a + 4) = *(const float4*)&As[kk][tm * 8 + 4];
            *(float4*)(b)     = *(const float4*)&Bs[kk][tn * 4];
            *(float4*)(b + 4) = *(const float4*)&Bs[kk][128 + tn * 4];
            #pragma unroll
            for (int i = 0; i < 8; i++)
                #pragma unroll
                for (int j = 0; j < 8; j++)
                    acc[i][j] = fmaf(a[i], b[j], acc[i][j]);
        }
    }

    const float* Rb = RES ? (resid + (size_t)bz * CDIM * HW) : nullptr;
    #pragma unroll
    for (int i = 0; i < 8; i++) {
        int m = m0 + tm * 8 + i;
        float bv = bias[m];
        size_t r0o = (size_t)m * HW + n0 + tn * 4;
        size_t r1o = r0o + 128;
        float4 o0, o1;
        o0.x = acc[i][0] + bv; o0.y = acc[i][1] + bv; o0.z = acc[i][2] + bv; o0.w = acc[i][3] + bv;
        o1.x = acc[i][4] + bv; o1.y = acc[i][5] + bv; o1.z = acc[i][6] + bv; o1.w = acc[i][7] + bv;
        if (RES) {
            float4 rv0 = *(const float4*)&Rb[r0o];
            float4 rv1 = *(const float4*)&Rb[r1o];
            o0.x += rv0.x; o0.y += rv0.y; o0.z += rv0.z; o0.w += rv0.w;
            o1.x += rv1.x; o1.y += rv1.y; o1.z += rv1.z; o1.w += rv1.w;
        }
        *(float4*)&Ob[r0o] = o0;
        *(float4*)&Ob[r1o] = o1;
    }
}

// ---------------- kernel 3: windowed cosine attention ----------------
// block = (window, 2 heads), 128 threads; thread n owns score row n of its head.
// S[64] in registers (bias preloaded); k/v staged [d][t] for broadcast LDS.
__global__ void __launch_bounds__(128) attn2(const float* __restrict__ logit_scale)
{
    __shared__ float qs[2][HD][64];
    __shared__ float ks[2][HD][64];
    __shared__ float vs[2][HD][64];

    const int tid = threadIdx.x;
    const int g = tid >> 6;          // head within pair
    const int n = tid & 63;          // token / score row
    const int wid = blockIdx.x;
    const int hp  = blockIdx.y;
    const int bz  = blockIdx.z;
    const int h   = hp * 2 + g;

    const int wy = wid >> 5, wx = wid & 31;
    const int spn = (wy * 8 + (n >> 3)) * 256 + wx * 8 + (n & 7);

    const size_t qkvbase = (size_t)bz * (3 * CDIM) * HW;
    const size_t obase   = (size_t)bz * CDIM * HW;

    // ---- stage q,k,v for this head: [d][t] layout, fully conflict-free STS ----
    {
        const float* qg = g_qkv + qkvbase + (size_t)(h * HD) * HW + spn;
        const float* kg = qg + (size_t)CDIM * HW;
        const float* vg = kg + (size_t)CDIM * HW;
        #pragma unroll
        for (int d = 0; d < HD; d++) qs[g][d][n] = qg[(size_t)d * HW];
        #pragma unroll
        for (int d = 0; d < HD; d++) ks[g][d][n] = kg[(size_t)d * HW];
        #pragma unroll
        for (int d = 0; d < HD; d++) vs[g][d][n] = vg[(size_t)d * HW];
    }

    // ---- bias row -> S registers ----
    float S[64];
    {
        const float4* brow = (const float4*)&g_bias[(h * 64 + n) * 64];
        #pragma unroll
        for (int i = 0; i < 16; i++) {
            float4 b4 = brow[i];
            S[4 * i + 0] = b4.x; S[4 * i + 1] = b4.y;
            S[4 * i + 2] = b4.z; S[4 * i + 3] = b4.w;
        }
    }
    __syncthreads();

    // ---- normalize k column n in place; compute q scale for row n ----
    const float LN100 = 4.6051701860f;
    const float scale_h = expf(fminf(logit_scale[h], LN100));
    {
        float ss = 0.f;
        #pragma unroll
        for (int d = 0; d < HD; d++) { float kv = ks[g][d][n]; ss = fmaf(kv, kv, ss); }
        float kinv = 1.f / fmaxf(sqrtf(ss), 1e-12f);
        #pragma unroll
        for (int d = 0; d < HD; d++) ks[g][d][n] *= kinv;
    }
    float qinv;
    {
        float ss = 0.f;
        #pragma unroll
        for (int d = 0; d < HD; d++) { float qv = qs[g][d][n]; ss = fmaf(qv, qv, ss); }
        qinv = scale_h / fmaxf(sqrtf(ss), 1e-12f);
    }
    __syncthreads();

    // ---- S[m] += (q[n].k[m]) : broadcast float4 reads of k[d][*] ----
    for (int d = 0; d < HD; d++) {
        float qd = qs[g][d][n] * qinv;
        const float4* kr = (const float4*)&ks[g][d][0];
        #pragma unroll
        for (int m4 = 0; m4 < 16; m4++) {
            float4 k4 = kr[m4];
            S[4 * m4 + 0] = fmaf(qd, k4.x, S[4 * m4 + 0]);
            S[4 * m4 + 1] = fmaf(qd, k4.y, S[4 * m4 + 1]);
            S[4 * m4 + 2] = fmaf(qd, k4.z, S[4 * m4 + 2]);
            S[4 * m4 + 3] = fmaf(qd, k4.w, S[4 * m4 + 3]);
        }
    }

    // ---- softmax over own row (registers only) ----
    float mx = -1e30f;
    #pragma unroll
    for (int m = 0; m < 64; m++) mx = fmaxf(mx, S[m]);
    float sum = 0.f;
    #pragma unroll
    for (int m = 0; m < 64; m++) { float e = __expf(S[m] - mx); S[m] = e; sum += e; }
    float pinv = 1.f / sum;

    // ---- out[n][d] = pinv * sum_m S[m] v[m][d] ; broadcast reads of v[d][*] ----
    float* og = g_att + obase + (size_t)(h * HD) * HW + spn;
    for (int d = 0; d < HD; d++) {
        const float4* vr = (const float4*)&vs[g][d][0];
        float acc = 0.f;
        #pragma unroll
        for (int m4 = 0; m4 < 16; m4++) {
            float4 v4 = vr[m4];
            acc = fmaf(S[4 * m4 + 0], v4.x, acc);
            acc = fmaf(S[4 * m4 + 1], v4.y, acc);
            acc = fmaf(S[4 * m4 + 2], v4.z, acc);
            acc = fmaf(S[4 * m4 + 3], v4.w, acc);
        }
        og[(size_t)d * HW] = acc * pinv;
    }
}

// ---------------- launch ----------------
extern "C" void kernel_launch(void* const* d_in, const int* in_sizes, int n_in,
                              void* d_out, int out_size)
{
    const float* x        = (const float*)d_in[0];
    const float* qkv_w    = (const float*)d_in[2];
    const float* q_bias   = (const float*)d_in[3];
    const float* v_bias   = (const float*)d_in[4];
    const float* lscale   = (const float*)d_in[5];
    const float* cpb_w1   = (const float*)d_in[6];
    const float* cpb_b1   = (const float*)d_in[7];
    const float* cpb_w2   = (const float*)d_in[8];
    const float* proj_w   = (const float*)d_in[9];
    const float* proj_b   = (const float*)d_in[10];
    float* out = (float*)d_out;

    float* qkv_buf; cudaGetSymbolAddress((void**)&qkv_buf, g_qkv);
    float* att_buf; cudaGetSymbolAddress((void**)&att_buf, g_att);
    float* qkvb;    cudaGetSymbolAddress((void**)&qkvb,    g_qkvb);

    bias_kernel<<<1, 256>>>(cpb_w1, cpb_b1, cpb_w2, q_bias, v_bias);

    // QKV: (576,192) @ (192,65536) per batch
    gemm2<false><<<dim3(HW / 256, (3 * CDIM) / 64, NB), 256>>>(
        qkv_w, qkvb, x, nullptr, qkv_buf, 3 * CDIM);

    // windowed cosine attention: 1024 windows x 4 head-pairs x 4 batch
    attn2<<<dim3(1024, NH / 2, NB), 128>>>(lscale);

    // proj + bias + residual -> output
    gemm2<true><<<dim3(HW / 256, CDIM / 64, NB), 256>>>(
        proj_w, proj_b, att_buf, x, out, CDIM);
}

// round 5
// speedup vs baseline: 2.1985x; 1.1057x over previous
#include <cuda_runtime.h>
#include <math.h>
#include <cstdint>

#define NH   8
#define HD   24
#define CDIM 192
#define HW   65536   // 256*256
#define NB   4
#define KDIM 192
#define MQ   640     // qkv rows padded to 5*128 (576 valid)
#define MP   256     // proj rows padded to 2*128 (192 valid)

#define SMEM_G 65536

// ---------------- device scratch ----------------
__device__ float    g_qkv[(size_t)NB * MQ * HW];    // (B, 640, 65536); rows >=576 unwritten
__device__ float    g_att[(size_t)NB * CDIM * HW];  // (B, 192, 65536)
__device__ float    g_bias[NH * 64 * 64];
__device__ unsigned g_wqf[MQ * KDIM];               // qkv weights, tf32, mma-fragment layout
__device__ unsigned g_wpf[MP * KDIM];               // proj weights, tf32, mma-fragment layout
__device__ float    g_bq[MQ];
__device__ float    g_bp[MP];

// ---------------- helpers ----------------
__device__ __forceinline__ uint32_t smem_u32(const void* p) {
    uint32_t a;
    asm("{ .reg .u64 t; cvta.to.shared.u64 t, %1; cvt.u32.u64 %0, t; }" : "=r"(a) : "l"(p));
    return a;
}
__device__ __forceinline__ uint32_t to_tf32(float f) {
    uint32_t u; asm("cvt.rna.tf32.f32 %0, %1;" : "=r"(u) : "f"(f)); return u;
}
__device__ __forceinline__ void lds128(uint32_t* r, uint32_t a) {
    asm volatile("ld.shared.v4.b32 {%0,%1,%2,%3}, [%4];"
                 : "=r"(r[0]), "=r"(r[1]), "=r"(r[2]), "=r"(r[3]) : "r"(a));
}
__device__ __forceinline__ void lds64(uint32_t* r, uint32_t a) {
    asm volatile("ld.shared.v2.b32 {%0,%1}, [%2];" : "=r"(r[0]), "=r"(r[1]) : "r"(a));
}
__device__ __forceinline__ void mma_tf32(float* c, const uint32_t* a, const uint32_t* b) {
    asm volatile("mma.sync.aligned.m16n8k8.row.col.f32.tf32.tf32.f32 "
                 "{%0,%1,%2,%3}, {%4,%5,%6,%7}, {%8,%9}, {%0,%1,%2,%3};"
                 : "+f"(c[0]), "+f"(c[1]), "+f"(c[2]), "+f"(c[3])
                 : "r"(a[0]), "r"(a[1]), "r"(a[2]), "r"(a[3]), "r"(b[0]), "r"(b[1]));
}

// ---------------- kernel 1: CPB bias table ----------------
__global__ void bias_kernel(const float* __restrict__ w1, const float* __restrict__ b1,
                            const float* __restrict__ w2)
{
    __shared__ float table[225][NH];
    int tid = threadIdx.x;

    if (tid < 225) {
        int a = tid / 15, b = tid % 15;
        const float inv_l8 = 1.0f / log2f(8.0f);
        float ca = (float)(a - 7) / 7.0f * 8.0f;
        float cb = (float)(b - 7) / 7.0f * 8.0f;
        float r0 = (ca == 0.f) ? 0.f : copysignf(log2f(fabsf(ca) + 1.0f) * inv_l8, ca);
        float r1 = (cb == 0.f) ? 0.f : copysignf(log2f(fabsf(cb) + 1.0f) * inv_l8, cb);
        float acc[NH];
        #pragma unroll
        for (int h = 0; h < NH; h++) acc[h] = 0.f;
        for (int j = 0; j < 512; j++) {
            float hv = fmaf(r0, w1[j], fmaf(r1, w1[512 + j], b1[j]));
            hv = fmaxf(hv, 0.f);
            #pragma unroll
            for (int h = 0; h < NH; h++) acc[h] = fmaf(hv, w2[j * NH + h], acc[h]);
        }
        #pragma unroll
        for (int h = 0; h < NH; h++) table[tid][h] = acc[h];
    }
    __syncthreads();

    for (int idx = tid; idx < NH * 64 * 64; idx += blockDim.x) {
        int h  = idx / (64 * 64);
        int nm = idx % (64 * 64);
        int n = nm / 64, m = nm % 64;
        int di = (n >> 3) - (m >> 3) + 7;
        int dj = (n & 7) - (m & 7) + 7;
        float t = table[di * 15 + dj][h];
        g_bias[idx] = 16.f / (1.f + expf(-t));
    }
}

// ---------------- kernel 1b: pack weights into tf32 mma-fragment layout ----------------
// layout per (mtile, kstage): 4096 elems = ((ks*8+mf)*32 + lane)*4 + slot
//   m = mt*128 + mf*16 + (lane>>2) + (slot&1)*8
//   k = kst*32 + ks*8 + (slot>>1)*4 + (lane&3)
__global__ void prep_kernel(const float* __restrict__ qkv_w, const float* __restrict__ qb,
                            const float* __restrict__ vb,
                            const float* __restrict__ proj_w, const float* __restrict__ pb)
{
    int i = blockIdx.x * blockDim.x + threadIdx.x;
    int stride = gridDim.x * blockDim.x;

    for (int idx = i; idx < MQ * KDIM; idx += stride) {
        int mt  = idx / (6 * 4096);
        int r   = idx % (6 * 4096);
        int kst = r / 4096;
        int r2  = r % 4096;
        int slot = r2 & 3, lane = (r2 >> 2) & 31, mf = (r2 >> 7) & 7, ks = r2 >> 10;
        int m = mt * 128 + mf * 16 + (lane >> 2) + (slot & 1) * 8;
        int k = kst * 32 + ks * 8 + (slot >> 1) * 4 + (lane & 3);
        float v = (m < 576) ? qkv_w[m * KDIM + k] : 0.f;
        g_wqf[idx] = to_tf32(v);
    }
    for (int idx = i; idx < MP * KDIM; idx += stride) {
        int mt  = idx / (6 * 4096);
        int r   = idx % (6 * 4096);
        int kst = r / 4096;
        int r2  = r % 4096;
        int slot = r2 & 3, lane = (r2 >> 2) & 31, mf = (r2 >> 7) & 7, ks = r2 >> 10;
        int m = mt * 128 + mf * 16 + (lane >> 2) + (slot & 1) * 8;
        int k = kst * 32 + ks * 8 + (slot >> 1) * 4 + (lane & 3);
        float v = (m < 192) ? proj_w[m * KDIM + k] : 0.f;
        g_wpf[idx] = to_tf32(v);
    }
    if (i < MQ) {
        float v = 0.f;
        if (i < 192)                  v = qb[i];
        else if (i >= 384 && i < 576) v = vb[i - 384];
        g_bq[i] = v;
    }
    if (i < MP) g_bp[i] = (i < 192) ? pb[i] : 0.f;
}

// ---------------- kernel 2/4: tf32 mma.sync GEMM ----------------
// C[M,HW] = W[M,192] @ X[192,HW] + bias (+resid)
// block 128x128, 512 thr (4x4 warps, 32x32 warp tile), BK=32 double-buffered.
// smem: A frag images [2][16KB] @0, B frag images [2][16KB] @32768.
template<bool RES>
__global__ void __launch_bounds__(512) gemm3(
    const unsigned* __restrict__ Af,  // fragment-packed weights
    const float* __restrict__ bias,
    const float* __restrict__ X,      // per batch: 192 x HW
    const float* __restrict__ resid,  // per batch: 192 x HW (RES only)
    float* __restrict__ out,
    int outRows, int Mvalid)
{
    extern __shared__ char sm[];
    const int tid = threadIdx.x;
    const int wid = tid >> 5, lane = tid & 31;
    const int wm = wid >> 2, wn = wid & 3;
    const int bz = blockIdx.z;
    const int m0 = blockIdx.x * 128;
    const int n0 = blockIdx.y * 128;
    const uint32_t sb = smem_u32(sm);

    const float* Xb = X + (size_t)bz * KDIM * HW + n0;
    const uint4* Afp = (const uint4*)(Af + (size_t)blockIdx.x * 6 * 4096);

    // B loader coords: lane-of-512 maps k = tid&31, n-group = (tid>>5)*8
    const int bk  = tid & 31;
    const int bnq = (tid >> 5) * 8;
    const float* Bg = Xb + (size_t)bk * HW + bnq;
    // precomputed B store base (bank-conflict-free via ks-XOR swizzle)
    const int bks   = bk >> 3;
    const int bnfg  = bnq >> 3;
    const uint32_t bstoreBase = ((bks * 16 + bnfg) * 32) * 8 + ((bk >> 2) & 1) * 4;
    uint32_t blaneoff[8];
    #pragma unroll
    for (int c = 0; c < 8; c++)
        blaneoff[c] = (uint32_t)(((c * 4 + (bk & 3)) ^ (bks << 2)) * 8);

    float acc[2][4][4];
    #pragma unroll
    for (int mf = 0; mf < 2; mf++)
        #pragma unroll
        for (int nf = 0; nf < 4; nf++)
            #pragma unroll
            for (int j = 0; j < 4; j++) acc[mf][nf][j] = 0.f;

    // ---- stage 0 ----
    {
        uint4 pa0 = Afp[tid], pa1 = Afp[tid + 512];
        float4 pb0 = *(const float4*)Bg;
        float4 pb1 = *(const float4*)(Bg + 4);
        *(uint4*)(sm + tid * 16)        = pa0;
        *(uint4*)(sm + 8192 + tid * 16) = pa1;
        char* bb = sm + 32768 + bstoreBase;
        *(uint32_t*)(bb + blaneoff[0]) = to_tf32(pb0.x);
        *(uint32_t*)(bb + blaneoff[1]) = to_tf32(pb0.y);
        *(uint32_t*)(bb + blaneoff[2]) = to_tf32(pb0.z);
        *(uint32_t*)(bb + blaneoff[3]) = to_tf32(pb0.w);
        *(uint32_t*)(bb + blaneoff[4]) = to_tf32(pb1.x);
        *(uint32_t*)(bb + blaneoff[5]) = to_tf32(pb1.y);
        *(uint32_t*)(bb + blaneoff[6]) = to_tf32(pb1.z);
        *(uint32_t*)(bb + blaneoff[7]) = to_tf32(pb1.w);
    }
    __syncthreads();

    #pragma unroll 1
    for (int s = 0; s < 6; s++) {
        const int buf = s & 1;

        // prefetch next stage (global -> regs)
        uint4 pa0, pa1; float4 pb0, pb1;
        if (s < 5) {
            pa0 = Afp[(s + 1) * 1024 + tid];
            pa1 = Afp[(s + 1) * 1024 + tid + 512];
            const float* bg = Bg + (size_t)(s + 1) * 32 * HW;
            pb0 = *(const float4*)bg;
            pb1 = *(const float4*)(bg + 4);
        }

        // compute current stage
        const uint32_t Ab = sb + buf * 16384;
        const uint32_t Bb = sb + 32768 + buf * 16384;
        #pragma unroll
        for (int ks = 0; ks < 4; ks++) {
            uint32_t a[2][4];
            lds128(a[0], Ab + ((ks * 8 + wm * 2 + 0) * 32 + lane) * 16);
            lds128(a[1], Ab + ((ks * 8 + wm * 2 + 1) * 32 + lane) * 16);
            uint32_t b[4][2];
            const int lr = lane ^ (ks << 2);
            #pragma unroll
            for (int nf = 0; nf < 4; nf++)
                lds64(b[nf], Bb + ((ks * 16 + wn * 4 + nf) * 32 + lr) * 8);
            #pragma unroll
            for (int mf = 0; mf < 2; mf++)
                #pragma unroll
                for (int nf = 0; nf < 4; nf++)
                    mma_tf32(acc[mf][nf], a[mf], b[nf]);
        }
        __syncthreads();

        if (s < 5) {
            const int nbuf = (s + 1) & 1;
            *(uint4*)(sm + nbuf * 16384 + tid * 16)        = pa0;
            *(uint4*)(sm + nbuf * 16384 + 8192 + tid * 16) = pa1;
            char* bb = sm + 32768 + nbuf * 16384 + bstoreBase;
            *(uint32_t*)(bb + blaneoff[0]) = to_tf32(pb0.x);
            *(uint32_t*)(bb + blaneoff[1]) = to_tf32(pb0.y);
            *(uint32_t*)(bb + blaneoff[2]) = to_tf32(pb0.z);
            *(uint32_t*)(bb + blaneoff[3]) = to_tf32(pb0.w);
            *(uint32_t*)(bb + blaneoff[4]) = to_tf32(pb1.x);
            *(uint32_t*)(bb + blaneoff[5]) = to_tf32(pb1.y);
            *(uint32_t*)(bb + blaneoff[6]) = to_tf32(pb1.z);
            *(uint32_t*)(bb + blaneoff[7]) = to_tf32(pb1.w);
            __syncthreads();
        }
    }

    // ---- epilogue ----
    const int gr = lane >> 2;
    const int qc = (lane & 3) * 2;
    float* outB = out + (size_t)bz * outRows * HW;
    const float* resB = resid + (size_t)bz * CDIM * HW;
    #pragma unroll
    for (int mf = 0; mf < 2; mf++) {
        #pragma unroll
        for (int hh = 0; hh < 2; hh++) {
            int m = m0 + wm * 32 + mf * 16 + gr + hh * 8;
            if (m < Mvalid) {
                float bv = bias[m];
                float* orow = outB + (size_t)m * HW + n0 + wn * 32 + qc;
                const float* rrow = resB + (size_t)m * HW + n0 + wn * 32 + qc;
                #pragma unroll
                for (int nf = 0; nf < 4; nf++) {
                    float2 o;
                    o.x = acc[mf][nf][hh * 2 + 0] + bv;
                    o.y = acc[mf][nf][hh * 2 + 1] + bv;
                    if (RES) {
                        float2 rv = *(const float2*)(rrow + nf * 8);
                        o.x += rv.x; o.y += rv.y;
                    }
                    *(float2*)(orow + nf * 8) = o;
                }
            }
        }
    }
}

// ---------------- kernel 3: windowed cosine attention (proven R3 version) ----------------
__global__ void __launch_bounds__(128) attn2(const float* __restrict__ logit_scale)
{
    __shared__ float qs[2][HD][64];
    __shared__ float ks[2][HD][64];
    __shared__ float vs[2][HD][64];

    const int tid = threadIdx.x;
    const int g = tid >> 6;
    const int n = tid & 63;
    const int wid = blockIdx.x;
    const int hp  = blockIdx.y;
    const int bz  = blockIdx.z;
    const int h   = hp * 2 + g;

    const int wy = wid >> 5, wx = wid & 31;
    const int spn = (wy * 8 + (n >> 3)) * 256 + wx * 8 + (n & 7);

    const size_t qkvbase = (size_t)bz * MQ * HW;
    const size_t obase   = (size_t)bz * CDIM * HW;

    {
        const float* qg = g_qkv + qkvbase + (size_t)(h * HD) * HW + spn;
        const float* kg = qg + (size_t)CDIM * HW;
        const float* vg = kg + (size_t)CDIM * HW;
        #pragma unroll
        for (int d = 0; d < HD; d++) qs[g][d][n] = qg[(size_t)d * HW];
        #pragma unroll
        for (int d = 0; d < HD; d++) ks[g][d][n] = kg[(size_t)d * HW];
        #pragma unroll
        for (int d = 0; d < HD; d++) vs[g][d][n] = vg[(size_t)d * HW];
    }

    float S[64];
    {
        const float4* brow = (const float4*)&g_bias[(h * 64 + n) * 64];
        #pragma unroll
        for (int i = 0; i < 16; i++) {
            float4 b4 = brow[i];
            S[4 * i + 0] = b4.x; S[4 * i + 1] = b4.y;
            S[4 * i + 2] = b4.z; S[4 * i + 3] = b4.w;
        }
    }
    __syncthreads();

    const float LN100 = 4.6051701860f;
    const float scale_h = expf(fminf(logit_scale[h], LN100));
    {
        float ss = 0.f;
        #pragma unroll
        for (int d = 0; d < HD; d++) { float kv = ks[g][d][n]; ss = fmaf(kv, kv, ss); }
        float kinv = 1.f / fmaxf(sqrtf(ss), 1e-12f);
        #pragma unroll
        for (int d = 0; d < HD; d++) ks[g][d][n] *= kinv;
    }
    float qinv;
    {
        float ss = 0.f;
        #pragma unroll
        for (int d = 0; d < HD; d++) { float qv = qs[g][d][n]; ss = fmaf(qv, qv, ss); }
        qinv = scale_h / fmaxf(sqrtf(ss), 1e-12f);
    }
    __syncthreads();

    for (int d = 0; d < HD; d++) {
        float qd = qs[g][d][n] * qinv;
        const float4* kr = (const float4*)&ks[g][d][0];
        #pragma unroll
        for (int m4 = 0; m4 < 16; m4++) {
            float4 k4 = kr[m4];
            S[4 * m4 + 0] = fmaf(qd, k4.x, S[4 * m4 + 0]);
            S[4 * m4 + 1] = fmaf(qd, k4.y, S[4 * m4 + 1]);
            S[4 * m4 + 2] = fmaf(qd, k4.z, S[4 * m4 + 2]);
            S[4 * m4 + 3] = fmaf(qd, k4.w, S[4 * m4 + 3]);
        }
    }

    float mx = -1e30f;
    #pragma unroll
    for (int m = 0; m < 64; m++) mx = fmaxf(mx, S[m]);
    float sum = 0.f;
    #pragma unroll
    for (int m = 0; m < 64; m++) { float e = __expf(S[m] - mx); S[m] = e; sum += e; }
    float pinv = 1.f / sum;

    float* og = g_att + obase + (size_t)(h * HD) * HW + spn;
    for (int d = 0; d < HD; d++) {
        const float4* vr = (const float4*)&vs[g][d][0];
        float a = 0.f;
        #pragma unroll
        for (int m4 = 0; m4 < 16; m4++) {
            float4 v4 = vr[m4];
            a = fmaf(S[4 * m4 + 0], v4.x, a);
            a = fmaf(S[4 * m4 + 1], v4.y, a);
            a = fmaf(S[4 * m4 + 2], v4.z, a);
            a = fmaf(S[4 * m4 + 3], v4.w, a);
        }
        og[(size_t)d * HW] = a * pinv;
    }
}

// ---------------- launch ----------------
extern "C" void kernel_launch(void* const* d_in, const int* in_sizes, int n_in,
                              void* d_out, int out_size)
{
    const float* x        = (const float*)d_in[0];
    const float* qkv_w    = (const float*)d_in[2];
    const float* q_bias   = (const float*)d_in[3];
    const float* v_bias   = (const float*)d_in[4];
    const float* lscale   = (const float*)d_in[5];
    const float* cpb_w1   = (const float*)d_in[6];
    const float* cpb_b1   = (const float*)d_in[7];
    const float* cpb_w2   = (const float*)d_in[8];
    const float* proj_w   = (const float*)d_in[9];
    const float* proj_b   = (const float*)d_in[10];
    float* out = (float*)d_out;

    float *qkv_buf, *att_buf, *bq, *bp;
    unsigned *wqf, *wpf;
    cudaGetSymbolAddress((void**)&qkv_buf, g_qkv);
    cudaGetSymbolAddress((void**)&att_buf, g_att);
    cudaGetSymbolAddress((void**)&wqf, g_wqf);
    cudaGetSymbolAddress((void**)&wpf, g_wpf);
    cudaGetSymbolAddress((void**)&bq, g_bq);
    cudaGetSymbolAddress((void**)&bp, g_bp);

    cudaFuncSetAttribute(gemm3<false>, cudaFuncAttributeMaxDynamicSharedMemorySize, SMEM_G);
    cudaFuncSetAttribute(gemm3<true>,  cudaFuncAttributeMaxDynamicSharedMemorySize, SMEM_G);

    bias_kernel<<<1, 256>>>(cpb_w1, cpb_b1, cpb_w2);
    prep_kernel<<<128, 256>>>(qkv_w, q_bias, v_bias, proj_w, proj_b);

    // QKV: 5 m-tiles x 512 n-tiles x 4 batch (m fastest for L2 reuse of X)
    gemm3<false><<<dim3(MQ / 128, HW / 128, NB), 512, SMEM_G>>>(
        wqf, bq, x, x, qkv_buf, MQ, 576);

    // windowed cosine attention
    attn2<<<dim3(1024, NH / 2, NB), 128>>>(lscale);

    // proj + bias + residual -> output
    gemm3<true><<<dim3(MP / 128, HW / 128, NB), 512, SMEM_G>>>(
        wpf, bp, att_buf, x, out, CDIM, 192);
}

// round 6
// speedup vs baseline: 2.4456x; 1.1124x over previous
#include <cuda_runtime.h>
#include <math.h>
#include <cstdint>

#define NH   8
#define HD   24
#define CDIM 192
#define HW   65536   // 256*256
#define NB   4
#define KDIM 192
#define MQ   640     // qkv rows padded to 5*128 (576 valid)
#define MP   256     // proj rows padded to 2*128 (192 valid)

// smem: A frag [2][16384] @0 ; B tile [2][32*136*4=17408] @32768
#define BPAD   136
#define BBUF   17408
#define SMEM_G 67584

// ---------------- device scratch ----------------
__device__ float    g_qkv[(size_t)NB * MQ * HW];    // (B, 640, 65536); rows >=576 unwritten
__device__ float    g_att[(size_t)NB * CDIM * HW];  // (B, 192, 65536)
__device__ float    g_bias[NH * 64 * 64];
__device__ unsigned g_wqf[MQ * KDIM];               // qkv weights, tf32, mma-fragment layout
__device__ unsigned g_wpf[MP * KDIM];               // proj weights, tf32, mma-fragment layout
__device__ float    g_bq[MQ];
__device__ float    g_bp[MP];

// ---------------- helpers ----------------
__device__ __forceinline__ uint32_t smem_u32(const void* p) {
    uint32_t a;
    asm("{ .reg .u64 t; cvta.to.shared.u64 t, %1; cvt.u32.u64 %0, t; }" : "=r"(a) : "l"(p));
    return a;
}
__device__ __forceinline__ uint32_t to_tf32(float f) {
    uint32_t u; asm("cvt.rna.tf32.f32 %0, %1;" : "=r"(u) : "f"(f)); return u;
}
__device__ __forceinline__ void lds128(uint32_t* r, uint32_t a) {
    asm volatile("ld.shared.v4.b32 {%0,%1,%2,%3}, [%4];"
                 : "=r"(r[0]), "=r"(r[1]), "=r"(r[2]), "=r"(r[3]) : "r"(a));
}
__device__ __forceinline__ uint32_t lds32(uint32_t a) {
    uint32_t r; asm volatile("ld.shared.b32 %0, [%1];" : "=r"(r) : "r"(a)); return r;
}
__device__ __forceinline__ void mma_tf32(float* c, const uint32_t* a, const uint32_t* b) {
    asm volatile("mma.sync.aligned.m16n8k8.row.col.f32.tf32.tf32.f32 "
                 "{%0,%1,%2,%3}, {%4,%5,%6,%7}, {%8,%9}, {%0,%1,%2,%3};"
                 : "+f"(c[0]), "+f"(c[1]), "+f"(c[2]), "+f"(c[3])
                 : "r"(a[0]), "r"(a[1]), "r"(a[2]), "r"(a[3]), "r"(b[0]), "r"(b[1]));
}

// ---------------- kernel 1: CPB bias table ----------------
__global__ void bias_kernel(const float* __restrict__ w1, const float* __restrict__ b1,
                            const float* __restrict__ w2)
{
    __shared__ float table[225][NH];
    int tid = threadIdx.x;

    if (tid < 225) {
        int a = tid / 15, b = tid % 15;
        const float inv_l8 = 1.0f / log2f(8.0f);
        float ca = (float)(a - 7) / 7.0f * 8.0f;
        float cb = (float)(b - 7) / 7.0f * 8.0f;
        float r0 = (ca == 0.f) ? 0.f : copysignf(log2f(fabsf(ca) + 1.0f) * inv_l8, ca);
        float r1 = (cb == 0.f) ? 0.f : copysignf(log2f(fabsf(cb) + 1.0f) * inv_l8, cb);
        float acc[NH];
        #pragma unroll
        for (int h = 0; h < NH; h++) acc[h] = 0.f;
        for (int j = 0; j < 512; j++) {
            float hv = fmaf(r0, w1[j], fmaf(r1, w1[512 + j], b1[j]));
            hv = fmaxf(hv, 0.f);
            #pragma unroll
            for (int h = 0; h < NH; h++) acc[h] = fmaf(hv, w2[j * NH + h], acc[h]);
        }
        #pragma unroll
        for (int h = 0; h < NH; h++) table[tid][h] = acc[h];
    }
    __syncthreads();

    for (int idx = tid; idx < NH * 64 * 64; idx += blockDim.x) {
        int h  = idx / (64 * 64);
        int nm = idx % (64 * 64);
        int n = nm / 64, m = nm % 64;
        int di = (n >> 3) - (m >> 3) + 7;
        int dj = (n & 7) - (m & 7) + 7;
        float t = table[di * 15 + dj][h];
        g_bias[idx] = 16.f / (1.f + expf(-t));
    }
}

// ---------------- kernel 1b: pack weights into tf32 mma-fragment layout ----------------
// layout per (mtile, kstage): 4096 elems = ((ks*8+mf)*32 + lane)*4 + slot
//   m = mt*128 + mf*16 + (lane>>2) + (slot&1)*8
//   k = kst*32 + ks*8 + (slot>>1)*4 + (lane&3)
__global__ void prep_kernel(const float* __restrict__ qkv_w, const float* __restrict__ qb,
                            const float* __restrict__ vb,
                            const float* __restrict__ proj_w, const float* __restrict__ pb)
{
    int i = blockIdx.x * blockDim.x + threadIdx.x;
    int stride = gridDim.x * blockDim.x;

    for (int idx = i; idx < MQ * KDIM; idx += stride) {
        int mt  = idx / (6 * 4096);
        int r   = idx % (6 * 4096);
        int kst = r / 4096;
        int r2  = r % 4096;
        int slot = r2 & 3, lane = (r2 >> 2) & 31, mf = (r2 >> 7) & 7, ks = r2 >> 10;
        int m = mt * 128 + mf * 16 + (lane >> 2) + (slot & 1) * 8;
        int k = kst * 32 + ks * 8 + (slot >> 1) * 4 + (lane & 3);
        float v = (m < 576) ? qkv_w[m * KDIM + k] : 0.f;
        g_wqf[idx] = to_tf32(v);
    }
    for (int idx = i; idx < MP * KDIM; idx += stride) {
        int mt  = idx / (6 * 4096);
        int r   = idx % (6 * 4096);
        int kst = r / 4096;
        int r2  = r % 4096;
        int slot = r2 & 3, lane = (r2 >> 2) & 31, mf = (r2 >> 7) & 7, ks = r2 >> 10;
        int m = mt * 128 + mf * 16 + (lane >> 2) + (slot & 1) * 8;
        int k = kst * 32 + ks * 8 + (slot >> 1) * 4 + (lane & 3);
        float v = (m < 192) ? proj_w[m * KDIM + k] : 0.f;
        g_wpf[idx] = to_tf32(v);
    }
    if (i < MQ) {
        float v = 0.f;
        if (i < 192)                  v = qb[i];
        else if (i >= 384 && i < 576) v = vb[i - 384];
        g_bq[i] = v;
    }
    if (i < MP) g_bp[i] = (i < 192) ? pb[i] : 0.f;
}

// ---------------- kernel 2/4: tf32 mma.sync GEMM ----------------
// C[M,HW] = W[M,192] @ X[192,HW] + bias (+resid)
// block 128x128, 512 thr (4x4 warps, 32x32 warp tile), BK=32 double-buffered.
// A: fragment images in smem (identity copy of pre-packed weights).
// B: plain padded [32][136] tile; coalesced LDG + conflict-free STS/LDS.
template<bool RES>
__global__ void __launch_bounds__(512) gemm3(
    const unsigned* __restrict__ Af,  // fragment-packed weights
    const float* __restrict__ bias,
    const float* __restrict__ X,      // per batch: 192 x HW
    const float* __restrict__ resid,  // per batch: 192 x HW (RES only)
    float* __restrict__ out,
    int outRows, int Mvalid)
{
    extern __shared__ char sm[];
    const int tid = threadIdx.x;
    const int wid = tid >> 5, lane = tid & 31;
    const int wm = wid >> 2, wn = wid & 3;
    const int bz = blockIdx.z;
    const int m0 = blockIdx.x * 128;
    const int n0 = blockIdx.y * 128;
    const uint32_t sb = smem_u32(sm);

    const float* Xb = X + (size_t)bz * KDIM * HW + n0;
    const uint4* Afp = (const uint4*)(Af + (size_t)blockIdx.x * 6 * 4096);

    // B loader: thread -> (row = tid>>4, cols = (tid&15)*8 .. +7) : coalesced
    const int brow = tid >> 4;
    const int bcol = (tid & 15) * 8;
    const float* Bg = Xb + (size_t)brow * HW + bcol;
    const uint32_t bsto = (uint32_t)(brow * BPAD + bcol) * 4;

    // B reader: b0 = B[ks*8 + (lane&3)][wn*32 + nf*8 + (lane>>2)], b1 = +4 rows
    const uint32_t brd = (uint32_t)(((lane & 3) * BPAD + wn * 32 + (lane >> 2)) * 4);

    float acc[2][4][4];
    #pragma unroll
    for (int mf = 0; mf < 2; mf++)
        #pragma unroll
        for (int nf = 0; nf < 4; nf++)
            #pragma unroll
            for (int j = 0; j < 4; j++) acc[mf][nf][j] = 0.f;

    // ---- stage 0 ----
    {
        uint4 pa0 = Afp[tid], pa1 = Afp[tid + 512];
        float4 pb0 = *(const float4*)Bg;
        float4 pb1 = *(const float4*)(Bg + 4);
        *(uint4*)(sm + tid * 16)        = pa0;
        *(uint4*)(sm + 8192 + tid * 16) = pa1;
        char* bb = sm + 32768 + bsto;
        uint4 t0, t1;
        t0.x = to_tf32(pb0.x); t0.y = to_tf32(pb0.y); t0.z = to_tf32(pb0.z); t0.w = to_tf32(pb0.w);
        t1.x = to_tf32(pb1.x); t1.y = to_tf32(pb1.y); t1.z = to_tf32(pb1.z); t1.w = to_tf32(pb1.w);
        *(uint4*)(bb)      = t0;
        *(uint4*)(bb + 16) = t1;
    }
    __syncthreads();

    #pragma unroll 1
    for (int s = 0; s < 6; s++) {
        const int buf = s & 1;

        // prefetch next stage (global -> regs)
        uint4 pa0, pa1; float4 pb0, pb1;
        if (s < 5) {
            pa0 = Afp[(s + 1) * 1024 + tid];
            pa1 = Afp[(s + 1) * 1024 + tid + 512];
            const float* bg = Bg + (size_t)(s + 1) * 32 * HW;
            pb0 = *(const float4*)bg;
            pb1 = *(const float4*)(bg + 4);
        }

        // compute current stage
        const uint32_t Ab = sb + buf * 16384;
        const uint32_t Bb = sb + 32768 + buf * BBUF + brd;
        #pragma unroll
        for (int ks = 0; ks < 4; ks++) {
            uint32_t a[2][4];
            lds128(a[0], Ab + ((ks * 8 + wm * 2 + 0) * 32 + lane) * 16);
            lds128(a[1], Ab + ((ks * 8 + wm * 2 + 1) * 32 + lane) * 16);
            uint32_t b[4][2];
            const uint32_t kbase = Bb + (uint32_t)(ks * 8 * BPAD * 4);
            #pragma unroll
            for (int nf = 0; nf < 4; nf++) {
                b[nf][0] = lds32(kbase + nf * 32);
                b[nf][1] = lds32(kbase + nf * 32 + 4 * BPAD * 4);
            }
            #pragma unroll
            for (int mf = 0; mf < 2; mf++)
                #pragma unroll
                for (int nf = 0; nf < 4; nf++)
                    mma_tf32(acc[mf][nf], a[mf], b[nf]);
        }
        __syncthreads();

        if (s < 5) {
            const int nbuf = (s + 1) & 1;
            *(uint4*)(sm + nbuf * 16384 + tid * 16)        = pa0;
            *(uint4*)(sm + nbuf * 16384 + 8192 + tid * 16) = pa1;
            char* bb = sm + 32768 + nbuf * BBUF + bsto;
            uint4 t0, t1;
            t0.x = to_tf32(pb0.x); t0.y = to_tf32(pb0.y); t0.z = to_tf32(pb0.z); t0.w = to_tf32(pb0.w);
            t1.x = to_tf32(pb1.x); t1.y = to_tf32(pb1.y); t1.z = to_tf32(pb1.z); t1.w = to_tf32(pb1.w);
            *(uint4*)(bb)      = t0;
            *(uint4*)(bb + 16) = t1;
            __syncthreads();
        }
    }

    // ---- epilogue ----
    const int gr = lane >> 2;
    const int qc = (lane & 3) * 2;
    float* outB = out + (size_t)bz * outRows * HW;
    const float* resB = resid + (size_t)bz * CDIM * HW;
    #pragma unroll
    for (int mf = 0; mf < 2; mf++) {
        #pragma unroll
        for (int hh = 0; hh < 2; hh++) {
            int m = m0 + wm * 32 + mf * 16 + gr + hh * 8;
            if (m < Mvalid) {
                float bv = bias[m];
                float* orow = outB + (size_t)m * HW + n0 + wn * 32 + qc;
                const float* rrow = resB + (size_t)m * HW + n0 + wn * 32 + qc;
                #pragma unroll
                for (int nf = 0; nf < 4; nf++) {
                    float2 o;
                    o.x = acc[mf][nf][hh * 2 + 0] + bv;
                    o.y = acc[mf][nf][hh * 2 + 1] + bv;
                    if (RES) {
                        float2 rv = *(const float2*)(rrow + nf * 8);
                        o.x += rv.x; o.y += rv.y;
                    }
                    *(float2*)(orow + nf * 8) = o;
                }
            }
        }
    }
}

// ---------------- kernel 3: windowed cosine attention (proven R3 version) ----------------
__global__ void __launch_bounds__(128) attn2(const float* __restrict__ logit_scale)
{
    __shared__ float qs[2][HD][64];
    __shared__ float ks[2][HD][64];
    __shared__ float vs[2][HD][64];

    const int tid = threadIdx.x;
    const int g = tid >> 6;
    const int n = tid & 63;
    const int wid = blockIdx.x;
    const int hp  = blockIdx.y;
    const int bz  = blockIdx.z;
    const int h   = hp * 2 + g;

    const int wy = wid >> 5, wx = wid & 31;
    const int spn = (wy * 8 + (n >> 3)) * 256 + wx * 8 + (n & 7);

    const size_t qkvbase = (size_t)bz * MQ * HW;
    const size_t obase   = (size_t)bz * CDIM * HW;

    {
        const float* qg = g_qkv + qkvbase + (size_t)(h * HD) * HW + spn;
        const float* kg = qg + (size_t)CDIM * HW;
        const float* vg = kg + (size_t)CDIM * HW;
        #pragma unroll
        for (int d = 0; d < HD; d++) qs[g][d][n] = qg[(size_t)d * HW];
        #pragma unroll
        for (int d = 0; d < HD; d++) ks[g][d][n] = kg[(size_t)d * HW];
        #pragma unroll
        for (int d = 0; d < HD; d++) vs[g][d][n] = vg[(size_t)d * HW];
    }

    float S[64];
    {
        const float4* brow = (const float4*)&g_bias[(h * 64 + n) * 64];
        #pragma unroll
        for (int i = 0; i < 16; i++) {
            float4 b4 = brow[i];
            S[4 * i + 0] = b4.x; S[4 * i + 1] = b4.y;
            S[4 * i + 2] = b4.z; S[4 * i + 3] = b4.w;
        }
    }
    __syncthreads();

    const float LN100 = 4.6051701860f;
    const float scale_h = expf(fminf(logit_scale[h], LN100));
    {
        float ss = 0.f;
        #pragma unroll
        for (int d = 0; d < HD; d++) { float kv = ks[g][d][n]; ss = fmaf(kv, kv, ss); }
        float kinv = 1.f / fmaxf(sqrtf(ss), 1e-12f);
        #pragma unroll
        for (int d = 0; d < HD; d++) ks[g][d][n] *= kinv;
    }
    float qinv;
    {
        float ss = 0.f;
        #pragma unroll
        for (int d = 0; d < HD; d++) { float qv = qs[g][d][n]; ss = fmaf(qv, qv, ss); }
        qinv = scale_h / fmaxf(sqrtf(ss), 1e-12f);
    }
    __syncthreads();

    for (int d = 0; d < HD; d++) {
        float qd = qs[g][d][n] * qinv;
        const float4* kr = (const float4*)&ks[g][d][0];
        #pragma unroll
        for (int m4 = 0; m4 < 16; m4++) {
            float4 k4 = kr[m4];
            S[4 * m4 + 0] = fmaf(qd, k4.x, S[4 * m4 + 0]);
            S[4 * m4 + 1] = fmaf(qd, k4.y, S[4 * m4 + 1]);
            S[4 * m4 + 2] = fmaf(qd, k4.z, S[4 * m4 + 2]);
            S[4 * m4 + 3] = fmaf(qd, k4.w, S[4 * m4 + 3]);
        }
    }

    float mx = -1e30f;
    #pragma unroll
    for (int m = 0; m < 64; m++) mx = fmaxf(mx, S[m]);
    float sum = 0.f;
    #pragma unroll
    for (int m = 0; m < 64; m++) { float e = __expf(S[m] - mx); S[m] = e; sum += e; }
    float pinv = 1.f / sum;

    float* og = g_att + obase + (size_t)(h * HD) * HW + spn;
    for (int d = 0; d < HD; d++) {
        const float4* vr = (const float4*)&vs[g][d][0];
        float a = 0.f;
        #pragma unroll
        for (int m4 = 0; m4 < 16; m4++) {
            float4 v4 = vr[m4];
            a = fmaf(S[4 * m4 + 0], v4.x, a);
            a = fmaf(S[4 * m4 + 1], v4.y, a);
            a = fmaf(S[4 * m4 + 2], v4.z, a);
            a = fmaf(S[4 * m4 + 3], v4.w, a);
        }
        og[(size_t)d * HW] = a * pinv;
    }
}

// ---------------- launch ----------------
extern "C" void kernel_launch(void* const* d_in, const int* in_sizes, int n_in,
                              void* d_out, int out_size)
{
    const float* x        = (const float*)d_in[0];
    const float* qkv_w    = (const float*)d_in[2];
    const float* q_bias   = (const float*)d_in[3];
    const float* v_bias   = (const float*)d_in[4];
    const float* lscale   = (const float*)d_in[5];
    const float* cpb_w1   = (const float*)d_in[6];
    const float* cpb_b1   = (const float*)d_in[7];
    const float* cpb_w2   = (const float*)d_in[8];
    const float* proj_w   = (const float*)d_in[9];
    const float* proj_b   = (const float*)d_in[10];
    float* out = (float*)d_out;

    float *qkv_buf, *att_buf, *bq, *bp;
    unsigned *wqf, *wpf;
    cudaGetSymbolAddress((void**)&qkv_buf, g_qkv);
    cudaGetSymbolAddress((void**)&att_buf, g_att);
    cudaGetSymbolAddress((void**)&wqf, g_wqf);
    cudaGetSymbolAddress((void**)&wpf, g_wpf);
    cudaGetSymbolAddress((void**)&bq, g_bq);
    cudaGetSymbolAddress((void**)&bp, g_bp);

    cudaFuncSetAttribute(gemm3<false>, cudaFuncAttributeMaxDynamicSharedMemorySize, SMEM_G);
    cudaFuncSetAttribute(gemm3<true>,  cudaFuncAttributeMaxDynamicSharedMemorySize, SMEM_G);

    bias_kernel<<<1, 256>>>(cpb_w1, cpb_b1, cpb_w2);
    prep_kernel<<<128, 256>>>(qkv_w, q_bias, v_bias, proj_w, proj_b);

    // QKV: 5 m-tiles x 512 n-tiles x 4 batch (m fastest for L2 reuse of X)
    gemm3<false><<<dim3(MQ / 128, HW / 128, NB), 512, SMEM_G>>>(
        wqf, bq, x, x, qkv_buf, MQ, 576);

    // windowed cosine attention
    attn2<<<dim3(1024, NH / 2, NB), 128>>>(lscale);

    // proj + bias + residual -> output
    gemm3<true><<<dim3(MP / 128, HW / 128, NB), 512, SMEM_G>>>(
        wpf, bp, att_buf, x, out, CDIM, 192);
}

// round 7
// speedup vs baseline: 2.7182x; 1.1115x over previous
#include <cuda_runtime.h>
#include <cuda_fp16.h>
#include <math.h>
#include <cstdint>

#define NH   8
#define HD   24
#define CDIM 192
#define HW   65536   // 256*256
#define NB   4
#define KDIM 192
#define MQ   640     // qkv rows padded to 5*128 (576 valid)
#define MP   256     // proj rows padded to 2*128 (192 valid)

// smem: A frag fp16 [2][8192] @0 ; B tile fp16 [2][32*136*2=8704] @16384
#define BPADH  136
#define BBUF   8704
#define SMEM_G 33792

// per m-tile packed-A footprint: 6 kstages * 2048 uint32
#define APM 12288

// ---------------- device scratch ----------------
__device__ float    g_qkv[(size_t)NB * MQ * HW];    // (B, 640, 65536); rows >=576 unwritten
__device__ float    g_att[(size_t)NB * CDIM * HW];  // (B, 192, 65536)
__device__ float    g_bias[NH * 64 * 64];
__device__ unsigned g_wqf[5 * APM];                 // qkv weights, fp16 frag layout
__device__ unsigned g_wpf[2 * APM];                 // proj weights, fp16 frag layout
__device__ float    g_bq[MQ];
__device__ float    g_bp[MP];

// ---------------- helpers ----------------
__device__ __forceinline__ uint32_t smem_u32(const void* p) {
    uint32_t a;
    asm("{ .reg .u64 t; cvta.to.shared.u64 t, %1; cvt.u32.u64 %0, t; }" : "=r"(a) : "l"(p));
    return a;
}
__device__ __forceinline__ void lds128(uint32_t* r, uint32_t a) {
    asm volatile("ld.shared.v4.b32 {%0,%1,%2,%3}, [%4];"
                 : "=r"(r[0]), "=r"(r[1]), "=r"(r[2]), "=r"(r[3]) : "r"(a));
}
__device__ __forceinline__ void ldmx4t(uint32_t* r, uint32_t a) {
    asm volatile("ldmatrix.sync.aligned.m8n8.x4.trans.shared.b16 {%0,%1,%2,%3}, [%4];"
                 : "=r"(r[0]), "=r"(r[1]), "=r"(r[2]), "=r"(r[3]) : "r"(a));
}
__device__ __forceinline__ void mma_f16(float* c, const uint32_t* a, const uint32_t* b) {
    asm volatile("mma.sync.aligned.m16n8k16.row.col.f32.f16.f16.f32 "
                 "{%0,%1,%2,%3}, {%4,%5,%6,%7}, {%8,%9}, {%0,%1,%2,%3};"
                 : "+f"(c[0]), "+f"(c[1]), "+f"(c[2]), "+f"(c[3])
                 : "r"(a[0]), "r"(a[1]), "r"(a[2]), "r"(a[3]), "r"(b[0]), "r"(b[1]));
}
__device__ __forceinline__ uint32_t pack_h2(float lo, float hi) {
    __half2 h = __floats2half2_rn(lo, hi);
    return *(uint32_t*)&h;
}

// ---------------- kernel 1: CPB bias table ----------------
__global__ void bias_kernel(const float* __restrict__ w1, const float* __restrict__ b1,
                            const float* __restrict__ w2)
{
    __shared__ float table[225][NH];
    int tid = threadIdx.x;

    if (tid < 225) {
        int a = tid / 15, b = tid % 15;
        const float inv_l8 = 1.0f / log2f(8.0f);
        float ca = (float)(a - 7) / 7.0f * 8.0f;
        float cb = (float)(b - 7) / 7.0f * 8.0f;
        float r0 = (ca == 0.f) ? 0.f : copysignf(log2f(fabsf(ca) + 1.0f) * inv_l8, ca);
        float r1 = (cb == 0.f) ? 0.f : copysignf(log2f(fabsf(cb) + 1.0f) * inv_l8, cb);
        float acc[NH];
        #pragma unroll
        for (int h = 0; h < NH; h++) acc[h] = 0.f;
        for (int j = 0; j < 512; j++) {
            float hv = fmaf(r0, w1[j], fmaf(r1, w1[512 + j], b1[j]));
            hv = fmaxf(hv, 0.f);
            #pragma unroll
            for (int h = 0; h < NH; h++) acc[h] = fmaf(hv, w2[j * NH + h], acc[h]);
        }
        #pragma unroll
        for (int h = 0; h < NH; h++) table[tid][h] = acc[h];
    }
    __syncthreads();

    for (int idx = tid; idx < NH * 64 * 64; idx += blockDim.x) {
        int h  = idx / (64 * 64);
        int nm = idx % (64 * 64);
        int n = nm / 64, m = nm % 64;
        int di = (n >> 3) - (m >> 3) + 7;
        int dj = (n & 7) - (m & 7) + 7;
        float t = table[di * 15 + dj][h];
        g_bias[idx] = 16.f / (1.f + expf(-t));
    }
}

// ---------------- kernel 1b: pack weights into fp16 m16n8k16 fragment layout ----------------
// per (mtile, kstage32): 2048 uint32 = ((ks*8+mf)*32 + lane)*4 + slot
//   each uint32 = half2 (k even, k odd):
//   m = mt*128 + mf*16 + (lane>>2) + (slot&1)*8
//   k = kst*32 + ks*16 + (lane&3)*2 + ((slot>>1)&1)*8  (+0/+1 for lo/hi half)
__global__ void prep_kernel(const float* __restrict__ qkv_w, const float* __restrict__ qb,
                            const float* __restrict__ vb,
                            const float* __restrict__ proj_w, const float* __restrict__ pb)
{
    int i = blockIdx.x * blockDim.x + threadIdx.x;
    int stride = gridDim.x * blockDim.x;

    for (int idx = i; idx < 5 * APM; idx += stride) {
        int mt  = idx / APM;
        int r   = idx % APM;
        int kst = r / 2048;
        int r2  = r % 2048;
        int slot = r2 & 3, lane = (r2 >> 2) & 31, mf = (r2 >> 7) & 7, ks = (r2 >> 10) & 1;
        int m = mt * 128 + mf * 16 + (lane >> 2) + (slot & 1) * 8;
        int k = kst * 32 + ks * 16 + (lane & 3) * 2 + ((slot >> 1) & 1) * 8;
        float v0 = (m < 576) ? qkv_w[m * KDIM + k]     : 0.f;
        float v1 = (m < 576) ? qkv_w[m * KDIM + k + 1] : 0.f;
        g_wqf[idx] = pack_h2(v0, v1);
    }
    for (int idx = i; idx < 2 * APM; idx += stride) {
        int mt  = idx / APM;
        int r   = idx % APM;
        int kst = r / 2048;
        int r2  = r % 2048;
        int slot = r2 & 3, lane = (r2 >> 2) & 31, mf = (r2 >> 7) & 7, ks = (r2 >> 10) & 1;
        int m = mt * 128 + mf * 16 + (lane >> 2) + (slot & 1) * 8;
        int k = kst * 32 + ks * 16 + (lane & 3) * 2 + ((slot >> 1) & 1) * 8;
        float v0 = (m < 192) ? proj_w[m * KDIM + k]     : 0.f;
        float v1 = (m < 192) ? proj_w[m * KDIM + k + 1] : 0.f;
        g_wpf[idx] = pack_h2(v0, v1);
    }
    if (i < MQ) {
        float v = 0.f;
        if (i < 192)                  v = qb[i];
        else if (i >= 384 && i < 576) v = vb[i - 384];
        g_bq[i] = v;
    }
    if (i < MP) g_bp[i] = (i < 192) ? pb[i] : 0.f;
}

// ---------------- kernel 2/4: fp16 mma.sync m16n8k16 GEMM ----------------
// C[M,HW] = W[M,192] @ X[192,HW] + bias (+resid)
// block 128x128, 512 thr (4x4 warps, 32x32 warp tile), BK=32 double-buffered.
template<bool RES>
__global__ void __launch_bounds__(512) gemm4(
    const unsigned* __restrict__ Af,  // fragment-packed fp16 weights
    const float* __restrict__ bias,
    const float* __restrict__ X,      // per batch: 192 x HW fp32
    const float* __restrict__ resid,  // per batch: 192 x HW (RES only)
    float* __restrict__ out,
    int outRows, int Mvalid)
{
    extern __shared__ char sm[];
    const int tid = threadIdx.x;
    const int wid = tid >> 5, lane = tid & 31;
    const int wm = wid >> 2, wn = wid & 3;
    const int bz = blockIdx.z;
    const int m0 = blockIdx.x * 128;
    const int n0 = blockIdx.y * 128;
    const uint32_t sb = smem_u32(sm);

    const float* Xb = X + (size_t)bz * KDIM * HW + n0;
    const uint4* Afp = (const uint4*)(Af + (size_t)blockIdx.x * APM);

    // B loader: thread -> (row k = tid>>4, cols n = (tid&15)*8 .. +7) coalesced
    const int brow = tid >> 4;
    const int bcol = (tid & 15) * 8;
    const float* Bg = Xb + (size_t)brow * HW + bcol;
    const uint32_t bsto = (uint32_t)(brow * BPADH + bcol) * 2;

    // ldmatrix lane address pieces: matrices {k-lo,k-hi}x{n-lo,n-hi}
    const int lrow = (lane & 7) + ((lane >> 3) & 1) * 8;
    const int lcol = ((lane >> 4) & 1) * 8;
    const uint32_t brd = (uint32_t)((lrow * BPADH + wn * 32 + lcol) * 2);

    float acc[2][4][4];
    #pragma unroll
    for (int mf = 0; mf < 2; mf++)
        #pragma unroll
        for (int nf = 0; nf < 4; nf++)
            #pragma unroll
            for (int j = 0; j < 4; j++) acc[mf][nf][j] = 0.f;

    // ---- stage 0 ----
    {
        uint4 pa = Afp[tid];
        float4 pb0 = *(const float4*)Bg;
        float4 pb1 = *(const float4*)(Bg + 4);
        *(uint4*)(sm + tid * 16) = pa;
        uint4 t;
        t.x = pack_h2(pb0.x, pb0.y); t.y = pack_h2(pb0.z, pb0.w);
        t.z = pack_h2(pb1.x, pb1.y); t.w = pack_h2(pb1.z, pb1.w);
        *(uint4*)(sm + 16384 + bsto) = t;
    }
    __syncthreads();

    #pragma unroll 1
    for (int s = 0; s < 6; s++) {
        const int buf = s & 1;

        // prefetch next stage (global -> regs)
        uint4 pa; float4 pb0, pb1;
        if (s < 5) {
            pa = Afp[(s + 1) * 512 + tid];
            const float* bg = Bg + (size_t)(s + 1) * 32 * HW;
            pb0 = *(const float4*)bg;
            pb1 = *(const float4*)(bg + 4);
        }

        // compute current stage: 2 k16 steps
        const uint32_t Ab = sb + buf * 8192;
        const uint32_t Bb = sb + 16384 + buf * BBUF + brd;
        #pragma unroll
        for (int ks = 0; ks < 2; ks++) {
            uint32_t a[2][4];
            lds128(a[0], Ab + ((ks * 8 + wm * 2 + 0) * 32 + lane) * 16);
            lds128(a[1], Ab + ((ks * 8 + wm * 2 + 1) * 32 + lane) * 16);
            uint32_t bm[2][4];   // [nf-pair][{b0lo,b1lo} for n-lo, {b0,b1} for n-hi]
            #pragma unroll
            for (int nfp = 0; nfp < 2; nfp++)
                ldmx4t(bm[nfp], Bb + (uint32_t)((ks * 16 * BPADH + nfp * 16) * 2));
            #pragma unroll
            for (int mf = 0; mf < 2; mf++)
                #pragma unroll
                for (int nf = 0; nf < 4; nf++)
                    mma_f16(acc[mf][nf], a[mf], &bm[nf >> 1][(nf & 1) * 2]);
        }
        __syncthreads();

        if (s < 5) {
            const int nbuf = (s + 1) & 1;
            *(uint4*)(sm + nbuf * 8192 + tid * 16) = pa;
            uint4 t;
            t.x = pack_h2(pb0.x, pb0.y); t.y = pack_h2(pb0.z, pb0.w);
            t.z = pack_h2(pb1.x, pb1.y); t.w = pack_h2(pb1.z, pb1.w);
            *(uint4*)(sm + 16384 + nbuf * BBUF + bsto) = t;
            __syncthreads();
        }
    }

    // ---- epilogue ----
    const int gr = lane >> 2;
    const int qc = (lane & 3) * 2;
    float* outB = out + (size_t)bz * outRows * HW;
    const float* resB = resid + (size_t)bz * CDIM * HW;
    #pragma unroll
    for (int mf = 0; mf < 2; mf++) {
        #pragma unroll
        for (int hh = 0; hh < 2; hh++) {
            int m = m0 + wm * 32 + mf * 16 + gr + hh * 8;
            if (m < Mvalid) {
                float bv = bias[m];
                float* orow = outB + (size_t)m * HW + n0 + wn * 32 + qc;
                const float* rrow = resB + (size_t)m * HW + n0 + wn * 32 + qc;
                #pragma unroll
                for (int nf = 0; nf < 4; nf++) {
                    float2 o;
                    o.x = acc[mf][nf][hh * 2 + 0] + bv;
                    o.y = acc[mf][nf][hh * 2 + 1] + bv;
                    if (RES) {
                        float2 rv = *(const float2*)(rrow + nf * 8);
                        o.x += rv.x; o.y += rv.y;
                    }
                    *(float2*)(orow + nf * 8) = o;
                }
            }
        }
    }
}

// ---------------- kernel 3: windowed cosine attention (proven R3 version) ----------------
__global__ void __launch_bounds__(128) attn2(const float* __restrict__ logit_scale)
{
    __shared__ float qs[2][HD][64];
    __shared__ float ks[2][HD][64];
    __shared__ float vs[2][HD][64];

    const int tid = threadIdx.x;
    const int g = tid >> 6;
    const int n = tid & 63;
    const int wid = blockIdx.x;
    const int hp  = blockIdx.y;
    const int bz  = blockIdx.z;
    const int h   = hp * 2 + g;

    const int wy = wid >> 5, wx = wid & 31;
    const int spn = (wy * 8 + (n >> 3)) * 256 + wx * 8 + (n & 7);

    const size_t qkvbase = (size_t)bz * MQ * HW;
    const size_t obase   = (size_t)bz * CDIM * HW;

    {
        const float* qg = g_qkv + qkvbase + (size_t)(h * HD) * HW + spn;
        const float* kg = qg + (size_t)CDIM * HW;
        const float* vg = kg + (size_t)CDIM * HW;
        #pragma unroll
        for (int d = 0; d < HD; d++) qs[g][d][n] = qg[(size_t)d * HW];
        #pragma unroll
        for (int d = 0; d < HD; d++) ks[g][d][n] = kg[(size_t)d * HW];
        #pragma unroll
        for (int d = 0; d < HD; d++) vs[g][d][n] = vg[(size_t)d * HW];
    }

    float S[64];
    {
        const float4* brow = (const float4*)&g_bias[(h * 64 + n) * 64];
        #pragma unroll
        for (int i = 0; i < 16; i++) {
            float4 b4 = brow[i];
            S[4 * i + 0] = b4.x; S[4 * i + 1] = b4.y;
            S[4 * i + 2] = b4.z; S[4 * i + 3] = b4.w;
        }
    }
    __syncthreads();

    const float LN100 = 4.6051701860f;
    const float scale_h = expf(fminf(logit_scale[h], LN100));
    {
        float ss = 0.f;
        #pragma unroll
        for (int d = 0; d < HD; d++) { float kv = ks[g][d][n]; ss = fmaf(kv, kv, ss); }
        float kinv = 1.f / fmaxf(sqrtf(ss), 1e-12f);
        #pragma unroll
        for (int d = 0; d < HD; d++) ks[g][d][n] *= kinv;
    }
    float qinv;
    {
        float ss = 0.f;
        #pragma unroll
        for (int d = 0; d < HD; d++) { float qv = qs[g][d][n]; ss = fmaf(qv, qv, ss); }
        qinv = scale_h / fmaxf(sqrtf(ss), 1e-12f);
    }
    __syncthreads();

    for (int d = 0; d < HD; d++) {
        float qd = qs[g][d][n] * qinv;
        const float4* kr = (const float4*)&ks[g][d][0];
        #pragma unroll
        for (int m4 = 0; m4 < 16; m4++) {
            float4 k4 = kr[m4];
            S[4 * m4 + 0] = fmaf(qd, k4.x, S[4 * m4 + 0]);
            S[4 * m4 + 1] = fmaf(qd, k4.y, S[4 * m4 + 1]);
            S[4 * m4 + 2] = fmaf(qd, k4.z, S[4 * m4 + 2]);
            S[4 * m4 + 3] = fmaf(qd, k4.w, S[4 * m4 + 3]);
        }
    }

    float mx = -1e30f;
    #pragma unroll
    for (int m = 0; m < 64; m++) mx = fmaxf(mx, S[m]);
    float sum = 0.f;
    #pragma unroll
    for (int m = 0; m < 64; m++) { float e = __expf(S[m] - mx); S[m] = e; sum += e; }
    float pinv = 1.f / sum;

    float* og = g_att + obase + (size_t)(h * HD) * HW + spn;
    for (int d = 0; d < HD; d++) {
        const float4* vr = (const float4*)&vs[g][d][0];
        float a = 0.f;
        #pragma unroll
        for (int m4 = 0; m4 < 16; m4++) {
            float4 v4 = vr[m4];
            a = fmaf(S[4 * m4 + 0], v4.x, a);
            a = fmaf(S[4 * m4 + 1], v4.y, a);
            a = fmaf(S[4 * m4 + 2], v4.z, a);
            a = fmaf(S[4 * m4 + 3], v4.w, a);
        }
        og[(size_t)d * HW] = a * pinv;
    }
}

// ---------------- launch ----------------
extern "C" void kernel_launch(void* const* d_in, const int* in_sizes, int n_in,
                              void* d_out, int out_size)
{
    const float* x        = (const float*)d_in[0];
    const float* qkv_w    = (const float*)d_in[2];
    const float* q_bias   = (const float*)d_in[3];
    const float* v_bias   = (const float*)d_in[4];
    const float* lscale   = (const float*)d_in[5];
    const float* cpb_w1   = (const float*)d_in[6];
    const float* cpb_b1   = (const float*)d_in[7];
    const float* cpb_w2   = (const float*)d_in[8];
    const float* proj_w   = (const float*)d_in[9];
    const float* proj_b   = (const float*)d_in[10];
    float* out = (float*)d_out;

    float *qkv_buf, *att_buf, *bq, *bp;
    unsigned *wqf, *wpf;
    cudaGetSymbolAddress((void**)&qkv_buf, g_qkv);
    cudaGetSymbolAddress((void**)&att_buf, g_att);
    cudaGetSymbolAddress((void**)&wqf, g_wqf);
    cudaGetSymbolAddress((void**)&wpf, g_wpf);
    cudaGetSymbolAddress((void**)&bq, g_bq);
    cudaGetSymbolAddress((void**)&bp, g_bp);

    cudaFuncSetAttribute(gemm4<false>, cudaFuncAttributeMaxDynamicSharedMemorySize, SMEM_G);
    cudaFuncSetAttribute(gemm4<true>,  cudaFuncAttributeMaxDynamicSharedMemorySize, SMEM_G);

    bias_kernel<<<1, 256>>>(cpb_w1, cpb_b1, cpb_w2);
    prep_kernel<<<128, 256>>>(qkv_w, q_bias, v_bias, proj_w, proj_b);

    // QKV: 5 m-tiles x 512 n-tiles x 4 batch (m fastest for L2 reuse of X)
    gemm4<false><<<dim3(MQ / 128, HW / 128, NB), 512, SMEM_G>>>(
        wqf, bq, x, x, qkv_buf, MQ, 576);

    // windowed cosine attention
    attn2<<<dim3(1024, NH / 2, NB), 128>>>(lscale);

    // proj + bias + residual -> output
    gemm4<true><<<dim3(MP / 128, HW / 128, NB), 512, SMEM_G>>>(
        wpf, bp, att_buf, x, out, CDIM, 192);
}

// round 8
// speedup vs baseline: 3.5309x; 1.2990x over previous
#include <cuda_runtime.h>
#include <cuda_fp16.h>
#include <math.h>
#include <cstdint>

#define NH   8
#define HD   24
#define CDIM 192
#define HW   65536   // 256*256
#define NB   4
#define KDIM 192
#define MQ   640     // qkv rows padded to 5*128 (576 valid)
#define MP   256     // proj rows padded to 2*128 (192 valid)

// GEMM smem: A frag fp16 [2][8192] @0 ; B tile fp16 [2][8704] @16384
#define BPADH  136
#define BBUF   8704
#define SMEM_G 33792
#define APM 12288

// ---------------- device scratch ----------------
__device__ float    g_qkv[(size_t)NB * MQ * HW];
__device__ float    g_att[(size_t)NB * CDIM * HW];
__device__ float    g_bias[NH * 64 * 64];
__device__ unsigned g_wqf[5 * APM];
__device__ unsigned g_wpf[2 * APM];
__device__ float    g_bq[MQ];
__device__ float    g_bp[MP];

// ---------------- helpers ----------------
__device__ __forceinline__ uint32_t smem_u32(const void* p) {
    uint32_t a;
    asm("{ .reg .u64 t; cvta.to.shared.u64 t, %1; cvt.u32.u64 %0, t; }" : "=r"(a) : "l"(p));
    return a;
}
__device__ __forceinline__ void lds128(uint32_t* r, uint32_t a) {
    asm volatile("ld.shared.v4.b32 {%0,%1,%2,%3}, [%4];"
                 : "=r"(r[0]), "=r"(r[1]), "=r"(r[2]), "=r"(r[3]) : "r"(a));
}
__device__ __forceinline__ void ldmx4(uint32_t* r, uint32_t a) {
    asm volatile("ldmatrix.sync.aligned.m8n8.x4.shared.b16 {%0,%1,%2,%3}, [%4];"
                 : "=r"(r[0]), "=r"(r[1]), "=r"(r[2]), "=r"(r[3]) : "r"(a));
}
__device__ __forceinline__ void ldmx4t(uint32_t* r, uint32_t a) {
    asm volatile("ldmatrix.sync.aligned.m8n8.x4.trans.shared.b16 {%0,%1,%2,%3}, [%4];"
                 : "=r"(r[0]), "=r"(r[1]), "=r"(r[2]), "=r"(r[3]) : "r"(a));
}
__device__ __forceinline__ void ldmx2t(uint32_t* r, uint32_t a) {
    asm volatile("ldmatrix.sync.aligned.m8n8.x2.trans.shared.b16 {%0,%1}, [%2];"
                 : "=r"(r[0]), "=r"(r[1]) : "r"(a));
}
__device__ __forceinline__ void mma_f16(float* c, const uint32_t* a, const uint32_t* b) {
    asm volatile("mma.sync.aligned.m16n8k16.row.col.f32.f16.f16.f32 "
                 "{%0,%1,%2,%3}, {%4,%5,%6,%7}, {%8,%9}, {%0,%1,%2,%3};"
                 : "+f"(c[0]), "+f"(c[1]), "+f"(c[2]), "+f"(c[3])
                 : "r"(a[0]), "r"(a[1]), "r"(a[2]), "r"(a[3]), "r"(b[0]), "r"(b[1]));
}
__device__ __forceinline__ uint32_t pack_h2(float lo, float hi) {
    __half2 h = __floats2half2_rn(lo, hi);
    return *(uint32_t*)&h;
}

// ---------------- kernel 1: CPB bias table ----------------
__global__ void bias_kernel(const float* __restrict__ w1, const float* __restrict__ b1,
                            const float* __restrict__ w2)
{
    __shared__ float table[225][NH];
    int tid = threadIdx.x;

    if (tid < 225) {
        int a = tid / 15, b = tid % 15;
        const float inv_l8 = 1.0f / log2f(8.0f);
        float ca = (float)(a - 7) / 7.0f * 8.0f;
        float cb = (float)(b - 7) / 7.0f * 8.0f;
        float r0 = (ca == 0.f) ? 0.f : copysignf(log2f(fabsf(ca) + 1.0f) * inv_l8, ca);
        float r1 = (cb == 0.f) ? 0.f : copysignf(log2f(fabsf(cb) + 1.0f) * inv_l8, cb);
        float acc[NH];
        #pragma unroll
        for (int h = 0; h < NH; h++) acc[h] = 0.f;
        for (int j = 0; j < 512; j++) {
            float hv = fmaf(r0, w1[j], fmaf(r1, w1[512 + j], b1[j]));
            hv = fmaxf(hv, 0.f);
            #pragma unroll
            for (int h = 0; h < NH; h++) acc[h] = fmaf(hv, w2[j * NH + h], acc[h]);
        }
        #pragma unroll
        for (int h = 0; h < NH; h++) table[tid][h] = acc[h];
    }
    __syncthreads();

    for (int idx = tid; idx < NH * 64 * 64; idx += blockDim.x) {
        int h  = idx / (64 * 64);
        int nm = idx % (64 * 64);
        int n = nm / 64, m = nm % 64;
        int di = (n >> 3) - (m >> 3) + 7;
        int dj = (n & 7) - (m & 7) + 7;
        float t = table[di * 15 + dj][h];
        g_bias[idx] = 16.f / (1.f + expf(-t));
    }
}

// ---------------- kernel 1b: pack weights into fp16 m16n8k16 fragment layout ----------------
__global__ void prep_kernel(const float* __restrict__ qkv_w, const float* __restrict__ qb,
                            const float* __restrict__ vb,
                            const float* __restrict__ proj_w, const float* __restrict__ pb)
{
    int i = blockIdx.x * blockDim.x + threadIdx.x;
    int stride = gridDim.x * blockDim.x;

    for (int idx = i; idx < 5 * APM; idx += stride) {
        int mt  = idx / APM;
        int r   = idx % APM;
        int kst = r / 2048;
        int r2  = r % 2048;
        int slot = r2 & 3, lane = (r2 >> 2) & 31, mf = (r2 >> 7) & 7, ks = (r2 >> 10) & 1;
        int m = mt * 128 + mf * 16 + (lane >> 2) + (slot & 1) * 8;
        int k = kst * 32 + ks * 16 + (lane & 3) * 2 + ((slot >> 1) & 1) * 8;
        float v0 = (m < 576) ? qkv_w[m * KDIM + k]     : 0.f;
        float v1 = (m < 576) ? qkv_w[m * KDIM + k + 1] : 0.f;
        g_wqf[idx] = pack_h2(v0, v1);
    }
    for (int idx = i; idx < 2 * APM; idx += stride) {
        int mt  = idx / APM;
        int r   = idx % APM;
        int kst = r / 2048;
        int r2  = r % 2048;
        int slot = r2 & 3, lane = (r2 >> 2) & 31, mf = (r2 >> 7) & 7, ks = (r2 >> 10) & 1;
        int m = mt * 128 + mf * 16 + (lane >> 2) + (slot & 1) * 8;
        int k = kst * 32 + ks * 16 + (lane & 3) * 2 + ((slot >> 1) & 1) * 8;
        float v0 = (m < 192) ? proj_w[m * KDIM + k]     : 0.f;
        float v1 = (m < 192) ? proj_w[m * KDIM + k + 1] : 0.f;
        g_wpf[idx] = pack_h2(v0, v1);
    }
    if (i < MQ) {
        float v = 0.f;
        if (i < 192)                  v = qb[i];
        else if (i >= 384 && i < 576) v = vb[i - 384];
        g_bq[i] = v;
    }
    if (i < MP) g_bp[i] = (i < 192) ? pb[i] : 0.f;
}

// ---------------- kernel 2/4: fp16 mma.sync m16n8k16 GEMM (unchanged from R7) ----------------
template<bool RES>
__global__ void __launch_bounds__(512) gemm4(
    const unsigned* __restrict__ Af,
    const float* __restrict__ bias,
    const float* __restrict__ X,
    const float* __restrict__ resid,
    float* __restrict__ out,
    int outRows, int Mvalid)
{
    extern __shared__ char sm[];
    const int tid = threadIdx.x;
    const int wid = tid >> 5, lane = tid & 31;
    const int wm = wid >> 2, wn = wid & 3;
    const int bz = blockIdx.z;
    const int m0 = blockIdx.x * 128;
    const int n0 = blockIdx.y * 128;
    const uint32_t sb = smem_u32(sm);

    const float* Xb = X + (size_t)bz * KDIM * HW + n0;
    const uint4* Afp = (const uint4*)(Af + (size_t)blockIdx.x * APM);

    const int brow = tid >> 4;
    const int bcol = (tid & 15) * 8;
    const float* Bg = Xb + (size_t)brow * HW + bcol;
    const uint32_t bsto = (uint32_t)(brow * BPADH + bcol) * 2;

    const int lrow = (lane & 7) + ((lane >> 3) & 1) * 8;
    const int lcol = ((lane >> 4) & 1) * 8;
    const uint32_t brd = (uint32_t)((lrow * BPADH + wn * 32 + lcol) * 2);

    float acc[2][4][4];
    #pragma unroll
    for (int mf = 0; mf < 2; mf++)
        #pragma unroll
        for (int nf = 0; nf < 4; nf++)
            #pragma unroll
            for (int j = 0; j < 4; j++) acc[mf][nf][j] = 0.f;

    {
        uint4 pa = Afp[tid];
        float4 pb0 = *(const float4*)Bg;
        float4 pb1 = *(const float4*)(Bg + 4);
        *(uint4*)(sm + tid * 16) = pa;
        uint4 t;
        t.x = pack_h2(pb0.x, pb0.y); t.y = pack_h2(pb0.z, pb0.w);
        t.z = pack_h2(pb1.x, pb1.y); t.w = pack_h2(pb1.z, pb1.w);
        *(uint4*)(sm + 16384 + bsto) = t;
    }
    __syncthreads();

    #pragma unroll 1
    for (int s = 0; s < 6; s++) {
        const int buf = s & 1;

        uint4 pa; float4 pb0, pb1;
        if (s < 5) {
            pa = Afp[(s + 1) * 512 + tid];
            const float* bg = Bg + (size_t)(s + 1) * 32 * HW;
            pb0 = *(const float4*)bg;
            pb1 = *(const float4*)(bg + 4);
        }

        const uint32_t Ab = sb + buf * 8192;
        const uint32_t Bb = sb + 16384 + buf * BBUF + brd;
        #pragma unroll
        for (int ks = 0; ks < 2; ks++) {
            uint32_t a[2][4];
            lds128(a[0], Ab + ((ks * 8 + wm * 2 + 0) * 32 + lane) * 16);
            lds128(a[1], Ab + ((ks * 8 + wm * 2 + 1) * 32 + lane) * 16);
            uint32_t bm[2][4];
            #pragma unroll
            for (int nfp = 0; nfp < 2; nfp++)
                ldmx4t(bm[nfp], Bb + (uint32_t)((ks * 16 * BPADH + nfp * 16) * 2));
            #pragma unroll
            for (int mf = 0; mf < 2; mf++)
                #pragma unroll
                for (int nf = 0; nf < 4; nf++)
                    mma_f16(acc[mf][nf], a[mf], &bm[nf >> 1][(nf & 1) * 2]);
        }
        __syncthreads();

        if (s < 5) {
            const int nbuf = (s + 1) & 1;
            *(uint4*)(sm + nbuf * 8192 + tid * 16) = pa;
            uint4 t;
            t.x = pack_h2(pb0.x, pb0.y); t.y = pack_h2(pb0.z, pb0.w);
            t.z = pack_h2(pb1.x, pb1.y); t.w = pack_h2(pb1.z, pb1.w);
            *(uint4*)(sm + 16384 + nbuf * BBUF + bsto) = t;
            __syncthreads();
        }
    }

    const int gr = lane >> 2;
    const int qc = (lane & 3) * 2;
    float* outB = out + (size_t)bz * outRows * HW;
    const float* resB = resid + (size_t)bz * CDIM * HW;
    #pragma unroll
    for (int mf = 0; mf < 2; mf++) {
        #pragma unroll
        for (int hh = 0; hh < 2; hh++) {
            int m = m0 + wm * 32 + mf * 16 + gr + hh * 8;
            if (m < Mvalid) {
                float bv = bias[m];
                float* orow = outB + (size_t)m * HW + n0 + wn * 32 + qc;
                const float* rrow = resB + (size_t)m * HW + n0 + wn * 32 + qc;
                #pragma unroll
                for (int nf = 0; nf < 4; nf++) {
                    float2 o;
                    o.x = acc[mf][nf][hh * 2 + 0] + bv;
                    o.y = acc[mf][nf][hh * 2 + 1] + bv;
                    if (RES) {
                        float2 rv = *(const float2*)(rrow + nf * 8);
                        o.x += rv.x; o.y += rv.y;
                    }
                    *(float2*)(orow + nf * 8) = o;
                }
            }
        }
    }
}

// ---------------- kernel 3: tensor-core windowed cosine attention ----------------
// block = (window, head), 128 threads / 4 warps; warp wr owns rows wr*16..wr*16+15.
__global__ void __launch_bounds__(128) attn3(const float* __restrict__ logit_scale)
{
    __shared__ __half qh[64 * 40];
    __shared__ __half kh[64 * 40];
    __shared__ __half vh[64 * 40];
    __shared__ float  osm[64 * 25];

    const int tid  = threadIdx.x;
    const int lane = tid & 31;
    const int wr   = tid >> 5;
    const int wid  = blockIdx.x;
    const int h    = blockIdx.y;
    const int bz   = blockIdx.z;
    const int wy = wid >> 5, wx = wid & 31;
    const int t = tid & 63, piece = tid >> 6;
    const int spn = (wy * 8 + (t >> 3)) * 256 + wx * 8 + (t & 7);

    const float LN100 = 4.6051701860f;
    const float scale_h = expf(fminf(logit_scale[h], LN100));

    // ---- gather + normalize -> fp16 smem [t][40] ----
    const float* gq = g_qkv + (size_t)bz * MQ * HW + (size_t)(h * HD) * HW + spn;
    if (piece == 0) {
        float row[HD]; float ss = 0.f;
        #pragma unroll
        for (int d = 0; d < HD; d++) { row[d] = gq[(size_t)d * HW]; ss = fmaf(row[d], row[d], ss); }
        float qinv = scale_h / fmaxf(sqrtf(ss), 1e-12f);
        #pragma unroll
        for (int d2 = 0; d2 < 12; d2++)
            *(__half2*)&qh[t * 40 + 2 * d2] = __floats2half2_rn(row[2 * d2] * qinv, row[2 * d2 + 1] * qinv);
        const float* gv = gq + (size_t)(2 * CDIM) * HW;
        #pragma unroll
        for (int d2 = 0; d2 < 6; d2++)
            *(__half2*)&vh[t * 40 + 2 * d2] = __floats2half2_rn(gv[(size_t)(2 * d2) * HW], gv[(size_t)(2 * d2 + 1) * HW]);
        *(uint4*)&qh[t * 40 + 24] = make_uint4(0, 0, 0, 0);
        *(uint4*)&vh[t * 40 + 24] = make_uint4(0, 0, 0, 0);
    } else {
        const float* gk = gq + (size_t)CDIM * HW;
        float row[HD]; float ss = 0.f;
        #pragma unroll
        for (int d = 0; d < HD; d++) { row[d] = gk[(size_t)d * HW]; ss = fmaf(row[d], row[d], ss); }
        float kinv = 1.f / fmaxf(sqrtf(ss), 1e-12f);
        #pragma unroll
        for (int d2 = 0; d2 < 12; d2++)
            *(__half2*)&kh[t * 40 + 2 * d2] = __floats2half2_rn(row[2 * d2] * kinv, row[2 * d2 + 1] * kinv);
        const float* gv = gq + (size_t)(2 * CDIM) * HW + (size_t)12 * HW;
        #pragma unroll
        for (int d2 = 0; d2 < 6; d2++)
            *(__half2*)&vh[t * 40 + 12 + 2 * d2] = __floats2half2_rn(gv[(size_t)(2 * d2) * HW], gv[(size_t)(2 * d2 + 1) * HW]);
        *(uint4*)&kh[t * 40 + 24] = make_uint4(0, 0, 0, 0);
    }
    __syncthreads();

    const uint32_t qb = smem_u32(qh), kb = smem_u32(kh), vb = smem_u32(vh);
    const int gr = lane >> 2;
    const int qc = (lane & 3) * 2;
    const int r0 = wr * 16 + gr, r1 = r0 + 8;

    // ---- S accumulators initialized with bias ----
    float S[8][4];
    #pragma unroll
    for (int nb = 0; nb < 8; nb++) {
        float2 b0 = *(const float2*)&g_bias[(h * 64 + r0) * 64 + nb * 8 + qc];
        float2 b1 = *(const float2*)&g_bias[(h * 64 + r1) * 64 + nb * 8 + qc];
        S[nb][0] = b0.x; S[nb][1] = b0.y; S[nb][2] = b1.x; S[nb][3] = b1.y;
    }

    // ---- S += Qn Kn^T (k = 32 padded) ----
    #pragma unroll
    for (int ks = 0; ks < 2; ks++) {
        uint32_t a[4];
        ldmx4(a, qb + (uint32_t)(((wr * 16 + (lane & 7) + ((lane >> 3) & 1) * 8) * 40
                                  + ks * 16 + (lane >> 4) * 8) * 2));
        #pragma unroll
        for (int nbp = 0; nbp < 4; nbp++) {
            uint32_t b[4];
            ldmx4(b, kb + (uint32_t)(((nbp * 16 + (lane & 7) + (lane >> 4) * 8) * 40
                                      + ks * 16 + ((lane >> 3) & 1) * 8) * 2));
            mma_f16(S[nbp * 2],     a, &b[0]);
            mma_f16(S[nbp * 2 + 1], a, &b[2]);
        }
    }

    // ---- softmax on fragments (rows r0, r1 per thread; quad reduction) ----
    float mx0 = -1e30f, mx1 = -1e30f;
    #pragma unroll
    for (int nb = 0; nb < 8; nb++) {
        mx0 = fmaxf(mx0, fmaxf(S[nb][0], S[nb][1]));
        mx1 = fmaxf(mx1, fmaxf(S[nb][2], S[nb][3]));
    }
    mx0 = fmaxf(mx0, __shfl_xor_sync(0xffffffffu, mx0, 1));
    mx0 = fmaxf(mx0, __shfl_xor_sync(0xffffffffu, mx0, 2));
    mx1 = fmaxf(mx1, __shfl_xor_sync(0xffffffffu, mx1, 1));
    mx1 = fmaxf(mx1, __shfl_xor_sync(0xffffffffu, mx1, 2));
    float s0 = 0.f, s1 = 0.f;
    #pragma unroll
    for (int nb = 0; nb < 8; nb++) {
        S[nb][0] = __expf(S[nb][0] - mx0); s0 += S[nb][0];
        S[nb][1] = __expf(S[nb][1] - mx0); s0 += S[nb][1];
        S[nb][2] = __expf(S[nb][2] - mx1); s1 += S[nb][2];
        S[nb][3] = __expf(S[nb][3] - mx1); s1 += S[nb][3];
    }
    s0 += __shfl_xor_sync(0xffffffffu, s0, 1);
    s0 += __shfl_xor_sync(0xffffffffu, s0, 2);
    s1 += __shfl_xor_sync(0xffffffffu, s1, 1);
    s1 += __shfl_xor_sync(0xffffffffu, s1, 2);
    float pinv0 = 1.f / s0, pinv1 = 1.f / s1;
    #pragma unroll
    for (int nb = 0; nb < 8; nb++) {
        S[nb][0] *= pinv0; S[nb][1] *= pinv0;
        S[nb][2] *= pinv1; S[nb][3] *= pinv1;
    }

    // ---- O = P @ V (k = 64 tokens, n = 24 dims) ----
    float O[3][4];
    #pragma unroll
    for (int nb3 = 0; nb3 < 3; nb3++)
        #pragma unroll
        for (int j = 0; j < 4; j++) O[nb3][j] = 0.f;

    #pragma unroll
    for (int kt = 0; kt < 4; kt++) {
        uint32_t a[4];
        a[0] = pack_h2(S[2 * kt][0],     S[2 * kt][1]);
        a[1] = pack_h2(S[2 * kt][2],     S[2 * kt][3]);
        a[2] = pack_h2(S[2 * kt + 1][0], S[2 * kt + 1][1]);
        a[3] = pack_h2(S[2 * kt + 1][2], S[2 * kt + 1][3]);
        uint32_t vrow = (uint32_t)(kt * 16 + (lane & 7) + ((lane >> 3) & 1) * 8) * 40;
        uint32_t b[4];
        ldmx4t(b, vb + (uint32_t)((vrow + (lane >> 4) * 8) * 2));
        mma_f16(O[0], a, &b[0]);
        mma_f16(O[1], a, &b[2]);
        uint32_t b2[2];
        ldmx2t(b2, vb + (uint32_t)((vrow + 16) * 2));
        mma_f16(O[2], a, b2);
    }

    // ---- O frags -> smem -> coalesced global write ----
    #pragma unroll
    for (int nb3 = 0; nb3 < 3; nb3++) {
        int d = nb3 * 8 + qc;
        osm[r0 * 25 + d]     = O[nb3][0];
        osm[r0 * 25 + d + 1] = O[nb3][1];
        osm[r1 * 25 + d]     = O[nb3][2];
        osm[r1 * 25 + d + 1] = O[nb3][3];
    }
    __syncthreads();

    float* og = g_att + (size_t)bz * CDIM * HW + (size_t)(h * HD) * HW + spn;
    const int d0 = piece * 12;
    #pragma unroll
    for (int d = 0; d < 12; d++)
        og[(size_t)(d0 + d) * HW] = osm[t * 25 + d0 + d];
}

// ---------------- launch ----------------
extern "C" void kernel_launch(void* const* d_in, const int* in_sizes, int n_in,
                              void* d_out, int out_size)
{
    const float* x        = (const float*)d_in[0];
    const float* qkv_w    = (const float*)d_in[2];
    const float* q_bias   = (const float*)d_in[3];
    const float* v_bias   = (const float*)d_in[4];
    const float* lscale   = (const float*)d_in[5];
    const float* cpb_w1   = (const float*)d_in[6];
    const float* cpb_b1   = (const float*)d_in[7];
    const float* cpb_w2   = (const float*)d_in[8];
    const float* proj_w   = (const float*)d_in[9];
    const float* proj_b   = (const float*)d_in[10];
    float* out = (float*)d_out;

    float *qkv_buf, *att_buf, *bq, *bp;
    unsigned *wqf, *wpf;
    cudaGetSymbolAddress((void**)&qkv_buf, g_qkv);
    cudaGetSymbolAddress((void**)&att_buf, g_att);
    cudaGetSymbolAddress((void**)&wqf, g_wqf);
    cudaGetSymbolAddress((void**)&wpf, g_wpf);
    cudaGetSymbolAddress((void**)&bq, g_bq);
    cudaGetSymbolAddress((void**)&bp, g_bp);

    cudaFuncSetAttribute(gemm4<false>, cudaFuncAttributeMaxDynamicSharedMemorySize, SMEM_G);
    cudaFuncSetAttribute(gemm4<true>,  cudaFuncAttributeMaxDynamicSharedMemorySize, SMEM_G);

    bias_kernel<<<1, 256>>>(cpb_w1, cpb_b1, cpb_w2);
    prep_kernel<<<128, 256>>>(qkv_w, q_bias, v_bias, proj_w, proj_b);

    gemm4<false><<<dim3(MQ / 128, HW / 128, NB), 512, SMEM_G>>>(
        wqf, bq, x, x, qkv_buf, MQ, 576);

    attn3<<<dim3(1024, NH, NB), 128>>>(lscale);

    gemm4<true><<<dim3(MP / 128, HW / 128, NB), 512, SMEM_G>>>(
        wpf, bp, att_buf, x, out, CDIM, 192);
}

// round 9
// speedup vs baseline: 4.0330x; 1.1422x over previous
#include <cuda_runtime.h>
#include <cuda_fp16.h>
#include <math.h>
#include <cstdint>

#define NH   8
#define HD   24
#define CDIM 192
#define HW   65536   // 256*256
#define NB   4
#define KDIM 192
#define MQ   640     // qkv rows padded to 5*128 (576 valid)
#define MP   256
#define NWIN 1024    // 32x32 windows

// GEMM smem: A frag fp16 [2][8192] @0 ; B tile fp16 [2][8704] @16384
#define BPADH  136
#define BBUF   8704
#define SMEM_G 33792
#define APM 12288

// ---------------- device scratch (fp16 window-native intermediates) ----------------
__device__ __half   g_qkvh[(size_t)NB * NWIN * 576 * 64];   // (B, win, ch, tok)
__device__ __half   g_atth[(size_t)NB * NWIN * CDIM * 64];  // (B, win, ch, tok)
__device__ float    g_bias[NH * 64 * 64];
__device__ unsigned g_wqf[5 * APM];
__device__ unsigned g_wpf[2 * APM];
__device__ float    g_bq[MQ];
__device__ float    g_bp[MP];

// ---------------- helpers ----------------
__device__ __forceinline__ uint32_t smem_u32(const void* p) {
    uint32_t a;
    asm("{ .reg .u64 t; cvta.to.shared.u64 t, %1; cvt.u32.u64 %0, t; }" : "=r"(a) : "l"(p));
    return a;
}
__device__ __forceinline__ void lds128(uint32_t* r, uint32_t a) {
    asm volatile("ld.shared.v4.b32 {%0,%1,%2,%3}, [%4];"
                 : "=r"(r[0]), "=r"(r[1]), "=r"(r[2]), "=r"(r[3]) : "r"(a));
}
__device__ __forceinline__ void ldmx4(uint32_t* r, uint32_t a) {
    asm volatile("ldmatrix.sync.aligned.m8n8.x4.shared.b16 {%0,%1,%2,%3}, [%4];"
                 : "=r"(r[0]), "=r"(r[1]), "=r"(r[2]), "=r"(r[3]) : "r"(a));
}
__device__ __forceinline__ void ldmx4t(uint32_t* r, uint32_t a) {
    asm volatile("ldmatrix.sync.aligned.m8n8.x4.trans.shared.b16 {%0,%1,%2,%3}, [%4];"
                 : "=r"(r[0]), "=r"(r[1]), "=r"(r[2]), "=r"(r[3]) : "r"(a));
}
__device__ __forceinline__ void ldmx2(uint32_t* r, uint32_t a) {
    asm volatile("ldmatrix.sync.aligned.m8n8.x2.shared.b16 {%0,%1}, [%2];"
                 : "=r"(r[0]), "=r"(r[1]) : "r"(a));
}
__device__ __forceinline__ void mma_f16(float* c, const uint32_t* a, const uint32_t* b) {
    asm volatile("mma.sync.aligned.m16n8k16.row.col.f32.f16.f16.f32 "
                 "{%0,%1,%2,%3}, {%4,%5,%6,%7}, {%8,%9}, {%0,%1,%2,%3};"
                 : "+f"(c[0]), "+f"(c[1]), "+f"(c[2]), "+f"(c[3])
                 : "r"(a[0]), "r"(a[1]), "r"(a[2]), "r"(a[3]), "r"(b[0]), "r"(b[1]));
}
__device__ __forceinline__ uint32_t pack_h2(float lo, float hi) {
    __half2 h = __floats2half2_rn(lo, hi);
    return *(uint32_t*)&h;
}

// ---------------- kernel 1: CPB bias table ----------------
__global__ void bias_kernel(const float* __restrict__ w1, const float* __restrict__ b1,
                            const float* __restrict__ w2)
{
    __shared__ float table[225][NH];
    int tid = threadIdx.x;

    if (tid < 225) {
        int a = tid / 15, b = tid % 15;
        const float inv_l8 = 1.0f / log2f(8.0f);
        float ca = (float)(a - 7) / 7.0f * 8.0f;
        float cb = (float)(b - 7) / 7.0f * 8.0f;
        float r0 = (ca == 0.f) ? 0.f : copysignf(log2f(fabsf(ca) + 1.0f) * inv_l8, ca);
        float r1 = (cb == 0.f) ? 0.f : copysignf(log2f(fabsf(cb) + 1.0f) * inv_l8, cb);
        float acc[NH];
        #pragma unroll
        for (int h = 0; h < NH; h++) acc[h] = 0.f;
        for (int j = 0; j < 512; j++) {
            float hv = fmaf(r0, w1[j], fmaf(r1, w1[512 + j], b1[j]));
            hv = fmaxf(hv, 0.f);
            #pragma unroll
            for (int h = 0; h < NH; h++) acc[h] = fmaf(hv, w2[j * NH + h], acc[h]);
        }
        #pragma unroll
        for (int h = 0; h < NH; h++) table[tid][h] = acc[h];
    }
    __syncthreads();

    for (int idx = tid; idx < NH * 64 * 64; idx += blockDim.x) {
        int h  = idx / (64 * 64);
        int nm = idx % (64 * 64);
        int n = nm / 64, m = nm % 64;
        int di = (n >> 3) - (m >> 3) + 7;
        int dj = (n & 7) - (m & 7) + 7;
        float t = table[di * 15 + dj][h];
        g_bias[idx] = 16.f / (1.f + expf(-t));
    }
}

// ---------------- kernel 1b: pack weights into fp16 m16n8k16 fragment layout ----------------
__global__ void prep_kernel(const float* __restrict__ qkv_w, const float* __restrict__ qb,
                            const float* __restrict__ vb,
                            const float* __restrict__ proj_w, const float* __restrict__ pb)
{
    int i = blockIdx.x * blockDim.x + threadIdx.x;
    int stride = gridDim.x * blockDim.x;

    for (int idx = i; idx < 5 * APM; idx += stride) {
        int mt  = idx / APM;
        int r   = idx % APM;
        int kst = r / 2048;
        int r2  = r % 2048;
        int slot = r2 & 3, lane = (r2 >> 2) & 31, mf = (r2 >> 7) & 7, ks = (r2 >> 10) & 1;
        int m = mt * 128 + mf * 16 + (lane >> 2) + (slot & 1) * 8;
        int k = kst * 32 + ks * 16 + (lane & 3) * 2 + ((slot >> 1) & 1) * 8;
        float v0 = (m < 576) ? qkv_w[m * KDIM + k]     : 0.f;
        float v1 = (m < 576) ? qkv_w[m * KDIM + k + 1] : 0.f;
        g_wqf[idx] = pack_h2(v0, v1);
    }
    for (int idx = i; idx < 2 * APM; idx += stride) {
        int mt  = idx / APM;
        int r   = idx % APM;
        int kst = r / 2048;
        int r2  = r % 2048;
        int slot = r2 & 3, lane = (r2 >> 2) & 31, mf = (r2 >> 7) & 7, ks = (r2 >> 10) & 1;
        int m = mt * 128 + mf * 16 + (lane >> 2) + (slot & 1) * 8;
        int k = kst * 32 + ks * 16 + (lane & 3) * 2 + ((slot >> 1) & 1) * 8;
        float v0 = (m < 192) ? proj_w[m * KDIM + k]     : 0.f;
        float v1 = (m < 192) ? proj_w[m * KDIM + k + 1] : 0.f;
        g_wpf[idx] = pack_h2(v0, v1);
    }
    if (i < MQ) {
        float v = 0.f;
        if (i < 192)                  v = qb[i];
        else if (i >= 384 && i < 576) v = vb[i - 384];
        g_bq[i] = v;
    }
    if (i < MP) g_bp[i] = (i < 192) ? pb[i] : 0.f;
}

// ---------------- kernel 2/4: fp16 mma.sync GEMM ----------------
// MODE 0 (QKV): B = fp32 X (pixel layout), out = fp16 window layout, no residual.
// MODE 1 (proj): B = fp16 g_att (window layout), out = fp32 pixel layout + residual.
template<int MODE>
__global__ void __launch_bounds__(512) gemm5(
    const unsigned* __restrict__ Af,
    const float* __restrict__ bias,
    const void* __restrict__ Bsrc,
    const float* __restrict__ resid,
    void* __restrict__ outp,
    int Mvalid)
{
    extern __shared__ char sm[];
    const int tid = threadIdx.x;
    const int wid = tid >> 5, lane = tid & 31;
    const int wm = wid >> 2, wn = wid & 3;
    const int bz = blockIdx.z;
    const int m0 = blockIdx.x * 128;
    const int n0 = blockIdx.y * 128;
    const uint32_t sb = smem_u32(sm);

    const uint4* Afp = (const uint4*)(Af + (size_t)blockIdx.x * APM);

    const int brow = tid >> 4;           // k row within stage
    const int bcol = (tid & 15) * 8;     // pixel offset within tile
    const uint32_t bsto = (uint32_t)(brow * BPADH + bcol) * 2;

    // window-layout coords for B loads / stores
    const int py = n0 >> 8;
    const int tok0 = (py & 7) * 8;

    const float* BgF = nullptr;
    const __half* BgH = nullptr;
    if (MODE == 0) {
        BgF = (const float*)Bsrc + (size_t)bz * KDIM * HW + n0 + (size_t)brow * HW + bcol;
    } else {
        int px = (n0 & 255) + bcol;
        int winb = ((py >> 3) << 5) + (px >> 3);
        BgH = (const __half*)Bsrc + (size_t)(bz * NWIN + winb) * CDIM * 64
              + (size_t)brow * 64 + tok0;
    }

    const int lrow = (lane & 7) + ((lane >> 3) & 1) * 8;
    const int lcol = ((lane >> 4) & 1) * 8;
    const uint32_t brd = (uint32_t)((lrow * BPADH + wn * 32 + lcol) * 2);

    float acc[2][4][4];
    #pragma unroll
    for (int mf = 0; mf < 2; mf++)
        #pragma unroll
        for (int nf = 0; nf < 4; nf++)
            #pragma unroll
            for (int j = 0; j < 4; j++) acc[mf][nf][j] = 0.f;

    // ---- stage 0 ----
    {
        uint4 pa = Afp[tid];
        uint4 t;
        if (MODE == 0) {
            float4 pb0 = *(const float4*)BgF;
            float4 pb1 = *(const float4*)(BgF + 4);
            t.x = pack_h2(pb0.x, pb0.y); t.y = pack_h2(pb0.z, pb0.w);
            t.z = pack_h2(pb1.x, pb1.y); t.w = pack_h2(pb1.z, pb1.w);
        } else {
            t = *(const uint4*)BgH;
        }
        *(uint4*)(sm + tid * 16) = pa;
        *(uint4*)(sm + 16384 + bsto) = t;
    }
    __syncthreads();

    #pragma unroll 1
    for (int s = 0; s < 6; s++) {
        const int buf = s & 1;

        uint4 pa; uint4 tnext;
        if (s < 5) {
            pa = Afp[(s + 1) * 512 + tid];
            if (MODE == 0) {
                const float* bg = BgF + (size_t)(s + 1) * 32 * HW;
                float4 pb0 = *(const float4*)bg;
                float4 pb1 = *(const float4*)(bg + 4);
                tnext.x = pack_h2(pb0.x, pb0.y); tnext.y = pack_h2(pb0.z, pb0.w);
                tnext.z = pack_h2(pb1.x, pb1.y); tnext.w = pack_h2(pb1.z, pb1.w);
            } else {
                tnext = *(const uint4*)(BgH + (size_t)(s + 1) * 32 * 64);
            }
        }

        const uint32_t Ab = sb + buf * 8192;
        const uint32_t Bb = sb + 16384 + buf * BBUF + brd;
        #pragma unroll
        for (int ks = 0; ks < 2; ks++) {
            uint32_t a[2][4];
            lds128(a[0], Ab + ((ks * 8 + wm * 2 + 0) * 32 + lane) * 16);
            lds128(a[1], Ab + ((ks * 8 + wm * 2 + 1) * 32 + lane) * 16);
            uint32_t bm[2][4];
            #pragma unroll
            for (int nfp = 0; nfp < 2; nfp++)
                ldmx4t(bm[nfp], Bb + (uint32_t)((ks * 16 * BPADH + nfp * 16) * 2));
            #pragma unroll
            for (int mf = 0; mf < 2; mf++)
                #pragma unroll
                for (int nf = 0; nf < 4; nf++)
                    mma_f16(acc[mf][nf], a[mf], &bm[nf >> 1][(nf & 1) * 2]);
        }
        __syncthreads();

        if (s < 5) {
            const int nbuf = (s + 1) & 1;
            *(uint4*)(sm + nbuf * 8192 + tid * 16) = pa;
            *(uint4*)(sm + 16384 + nbuf * BBUF + bsto) = tnext;
            __syncthreads();
        }
    }

    // ---- epilogue ----
    const int gr = lane >> 2;
    const int qc = (lane & 3) * 2;

    if (MODE == 0) {
        // fp16 window-layout store
        int win[4], tok[4];
        #pragma unroll
        for (int nf = 0; nf < 4; nf++) {
            int px = (n0 & 255) + wn * 32 + nf * 8 + qc;
            win[nf] = ((py >> 3) << 5) + (px >> 3);
            tok[nf] = (py & 7) * 8 + (px & 7);
        }
        __half* outW = (__half*)outp + (size_t)bz * NWIN * 576 * 64;
        #pragma unroll
        for (int mf = 0; mf < 2; mf++) {
            #pragma unroll
            for (int hh = 0; hh < 2; hh++) {
                int m = m0 + wm * 32 + mf * 16 + gr + hh * 8;
                if (m < Mvalid) {
                    float bv = bias[m];
                    #pragma unroll
                    for (int nf = 0; nf < 4; nf++) {
                        __half2 o = __floats2half2_rn(acc[mf][nf][hh * 2 + 0] + bv,
                                                      acc[mf][nf][hh * 2 + 1] + bv);
                        *(__half2*)&outW[((size_t)win[nf] * 576 + m) * 64 + tok[nf]] = o;
                    }
                }
            }
        }
    } else {
        float* outB = (float*)outp + (size_t)bz * CDIM * HW;
        const float* resB = resid + (size_t)bz * CDIM * HW;
        #pragma unroll
        for (int mf = 0; mf < 2; mf++) {
            #pragma unroll
            for (int hh = 0; hh < 2; hh++) {
                int m = m0 + wm * 32 + mf * 16 + gr + hh * 8;
                if (m < Mvalid) {
                    float bv = bias[m];
                    float* orow = outB + (size_t)m * HW + n0 + wn * 32 + qc;
                    const float* rrow = resB + (size_t)m * HW + n0 + wn * 32 + qc;
                    #pragma unroll
                    for (int nf = 0; nf < 4; nf++) {
                        float2 o;
                        o.x = acc[mf][nf][hh * 2 + 0] + bv;
                        o.y = acc[mf][nf][hh * 2 + 1] + bv;
                        float2 rv = *(const float2*)(rrow + nf * 8);
                        o.x += rv.x; o.y += rv.y;
                        *(float2*)(orow + nf * 8) = o;
                    }
                }
            }
        }
    }
}

// ---------------- kernel 3: tensor-core attention on window-native fp16 ----------------
// block = (window, head), 128 threads / 4 warps. q/k/v stored [d][t] in smem.
__global__ void __launch_bounds__(128) attn4(const float* __restrict__ logit_scale)
{
    __shared__ __half qs_[32 * 72];
    __shared__ __half ks_[32 * 72];
    __shared__ __half vs_[24 * 72];
    __shared__ __half os_[24 * 72];
    __shared__ float qn[64], kn[64];

    const int tid  = threadIdx.x;
    const int lane = tid & 31;
    const int wr   = tid >> 5;
    const int win  = blockIdx.x;
    const int h    = blockIdx.y;
    const int bz   = blockIdx.z;

    const float LN100 = 4.6051701860f;
    const float scale_h = expf(fminf(logit_scale[h], LN100));

    // ---- contiguous loads: q/k/v = 24x64 half each ----
    const __half* gq = g_qkvh + ((size_t)(bz * NWIN + win) * 576 + h * HD) * 64;
    #pragma unroll
    for (int pass = 0; pass < 5; pass++) {
        int idx = tid + pass * 128;
        if (idx < 576) {
            int arr = idx / 192, rem = idx % 192;
            int d = rem >> 3, tg = rem & 7;
            uint4 val = *(const uint4*)(gq + (size_t)arr * 192 * 64 + d * 64 + tg * 8);
            __half* dst = (arr == 0) ? qs_ : (arr == 1) ? ks_ : vs_;
            *(uint4*)&dst[d * 72 + tg * 8] = val;
        }
    }
    {   // zero-pad q,k rows 24..31 (k-dim padding for the S mma)
        int arr2 = tid >> 6, rr = (tid >> 3) & 7, tg = tid & 7;
        __half* dst = arr2 ? ks_ : qs_;
        *(uint4*)&dst[(24 + rr) * 72 + tg * 8] = make_uint4(0, 0, 0, 0);
    }
    __syncthreads();

    // ---- per-token inverse norms ----
    {
        int t = tid & 63;
        const __half* col = (tid < 64) ? qs_ : ks_;
        float ss = 0.f;
        #pragma unroll
        for (int d = 0; d < HD; d++) {
            float f = __half2float(col[d * 72 + t]);
            ss = fmaf(f, f, ss);
        }
        float inv = 1.f / fmaxf(sqrtf(ss), 1e-12f);
        if (tid < 64) qn[t] = inv * scale_h; else kn[t] = inv;
    }
    __syncthreads();

    const uint32_t qb = smem_u32(qs_), kb = smem_u32(ks_), vb = smem_u32(vs_);
    const int gr = lane >> 2;
    const int qc = (lane & 3) * 2;
    const int r0 = wr * 16 + gr, r1 = r0 + 8;

    // ---- S = Qraw Kraw^T (k over dims, padded to 32) ----
    float S[8][4];
    #pragma unroll
    for (int nb = 0; nb < 8; nb++)
        #pragma unroll
        for (int j = 0; j < 4; j++) S[nb][j] = 0.f;

    #pragma unroll
    for (int ks = 0; ks < 2; ks++) {
        uint32_t a[4];
        // A (trans from [d][t]): bit3 -> t+8 (mat1), bit4 -> d+8 (mat2)
        ldmx4t(a, qb + (uint32_t)(((ks * 16 + (lane & 7) + ((lane >> 4) & 1) * 8) * 72
                                   + wr * 16 + ((lane >> 3) & 1) * 8) * 2));
        #pragma unroll
        for (int nbp = 0; nbp < 4; nbp++) {
            uint32_t b[4];
            // B (trans from [d][t]): bit3 -> d+8 (k-hi, mat1), bit4 -> t+8 (n-hi, mat2)
            ldmx4t(b, kb + (uint32_t)(((ks * 16 + (lane & 7) + ((lane >> 3) & 1) * 8) * 72
                                       + nbp * 16 + ((lane >> 4) & 1) * 8) * 2));
            mma_f16(S[nbp * 2],     a, &b[0]);
            mma_f16(S[nbp * 2 + 1], a, &b[2]);
        }
    }

    // ---- scale by qn*kn, add bias ----
    const float qn0 = qn[r0], qn1 = qn[r1];
    #pragma unroll
    for (int nb = 0; nb < 8; nb++) {
        int c0 = nb * 8 + qc;
        float k0v = kn[c0], k1v = kn[c0 + 1];
        float2 b0 = *(const float2*)&g_bias[(h * 64 + r0) * 64 + c0];
        float2 b1 = *(const float2*)&g_bias[(h * 64 + r1) * 64 + c0];
        S[nb][0] = S[nb][0] * qn0 * k0v + b0.x;
        S[nb][1] = S[nb][1] * qn0 * k1v + b0.y;
        S[nb][2] = S[nb][2] * qn1 * k0v + b1.x;
        S[nb][3] = S[nb][3] * qn1 * k1v + b1.y;
    }

    // ---- softmax (quad reduction, rows r0/r1) ----
    float mx0 = -1e30f, mx1 = -1e30f;
    #pragma unroll
    for (int nb = 0; nb < 8; nb++) {
        mx0 = fmaxf(mx0, fmaxf(S[nb][0], S[nb][1]));
        mx1 = fmaxf(mx1, fmaxf(S[nb][2], S[nb][3]));
    }
    mx0 = fmaxf(mx0, __shfl_xor_sync(0xffffffffu, mx0, 1));
    mx0 = fmaxf(mx0, __shfl_xor_sync(0xffffffffu, mx0, 2));
    mx1 = fmaxf(mx1, __shfl_xor_sync(0xffffffffu, mx1, 1));
    mx1 = fmaxf(mx1, __shfl_xor_sync(0xffffffffu, mx1, 2));
    float s0 = 0.f, s1 = 0.f;
    #pragma unroll
    for (int nb = 0; nb < 8; nb++) {
        S[nb][0] = __expf(S[nb][0] - mx0); s0 += S[nb][0];
        S[nb][1] = __expf(S[nb][1] - mx0); s0 += S[nb][1];
        S[nb][2] = __expf(S[nb][2] - mx1); s1 += S[nb][2];
        S[nb][3] = __expf(S[nb][3] - mx1); s1 += S[nb][3];
    }
    s0 += __shfl_xor_sync(0xffffffffu, s0, 1);
    s0 += __shfl_xor_sync(0xffffffffu, s0, 2);
    s1 += __shfl_xor_sync(0xffffffffu, s1, 1);
    s1 += __shfl_xor_sync(0xffffffffu, s1, 2);
    float pinv0 = 1.f / s0, pinv1 = 1.f / s1;
    #pragma unroll
    for (int nb = 0; nb < 8; nb++) {
        S[nb][0] *= pinv0; S[nb][1] *= pinv0;
        S[nb][2] *= pinv1; S[nb][3] *= pinv1;
    }

    // ---- O = P @ V (V stored [d][t] = col-major B, non-trans ldmatrix) ----
    float O[3][4];
    #pragma unroll
    for (int nb3 = 0; nb3 < 3; nb3++)
        #pragma unroll
        for (int j = 0; j < 4; j++) O[nb3][j] = 0.f;

    #pragma unroll
    for (int kt = 0; kt < 4; kt++) {
        uint32_t a[4];
        a[0] = pack_h2(S[2 * kt][0],     S[2 * kt][1]);
        a[1] = pack_h2(S[2 * kt][2],     S[2 * kt][3]);
        a[2] = pack_h2(S[2 * kt + 1][0], S[2 * kt + 1][1]);
        a[3] = pack_h2(S[2 * kt + 1][2], S[2 * kt + 1][3]);
        uint32_t b[4];
        // rows d (n), cols t (k); bit3 -> k-hi, bit4 -> n-hi
        ldmx4(b, vb + (uint32_t)((((lane & 7) + ((lane >> 4) & 1) * 8) * 72
                                   + kt * 16 + ((lane >> 3) & 1) * 8) * 2));
        mma_f16(O[0], a, &b[0]);
        mma_f16(O[1], a, &b[2]);
        uint32_t b2[2];
        ldmx2(b2, vb + (uint32_t)(((16 + (lane & 7)) * 72
                                    + kt * 16 + (((lane & 15) >> 3) & 1) * 8) * 2));
        mma_f16(O[2], a, b2);
    }

    // ---- O frags -> smem [d][t] -> contiguous global write ----
    #pragma unroll
    for (int nb3 = 0; nb3 < 3; nb3++) {
        int d = nb3 * 8 + qc;
        os_[d * 72 + r0]       = __float2half(O[nb3][0]);
        os_[(d + 1) * 72 + r0] = __float2half(O[nb3][1]);
        os_[d * 72 + r1]       = __float2half(O[nb3][2]);
        os_[(d + 1) * 72 + r1] = __float2half(O[nb3][3]);
    }
    __syncthreads();

    __half* ga = g_atth + ((size_t)(bz * NWIN + win) * CDIM + h * HD) * 64;
    #pragma unroll
    for (int pass = 0; pass < 2; pass++) {
        int idx = tid + pass * 128;
        if (idx < 192) {
            int d = idx >> 3, tg = idx & 7;
            *(uint4*)(ga + d * 64 + tg * 8) = *(uint4*)&os_[d * 72 + tg * 8];
        }
    }
}

// ---------------- launch ----------------
extern "C" void kernel_launch(void* const* d_in, const int* in_sizes, int n_in,
                              void* d_out, int out_size)
{
    const float* x        = (const float*)d_in[0];
    const float* qkv_w    = (const float*)d_in[2];
    const float* q_bias   = (const float*)d_in[3];
    const float* v_bias   = (const float*)d_in[4];
    const float* lscale   = (const float*)d_in[5];
    const float* cpb_w1   = (const float*)d_in[6];
    const float* cpb_b1   = (const float*)d_in[7];
    const float* cpb_w2   = (const float*)d_in[8];
    const float* proj_w   = (const float*)d_in[9];
    const float* proj_b   = (const float*)d_in[10];
    float* out = (float*)d_out;

    __half *qkv_buf, *att_buf;
    float *bq, *bp;
    unsigned *wqf, *wpf;
    cudaGetSymbolAddress((void**)&qkv_buf, g_qkvh);
    cudaGetSymbolAddress((void**)&att_buf, g_atth);
    cudaGetSymbolAddress((void**)&wqf, g_wqf);
    cudaGetSymbolAddress((void**)&wpf, g_wpf);
    cudaGetSymbolAddress((void**)&bq, g_bq);
    cudaGetSymbolAddress((void**)&bp, g_bp);

    cudaFuncSetAttribute(gemm5<0>, cudaFuncAttributeMaxDynamicSharedMemorySize, SMEM_G);
    cudaFuncSetAttribute(gemm5<1>, cudaFuncAttributeMaxDynamicSharedMemorySize, SMEM_G);

    bias_kernel<<<1, 256>>>(cpb_w1, cpb_b1, cpb_w2);
    prep_kernel<<<128, 256>>>(qkv_w, q_bias, v_bias, proj_w, proj_b);

    // QKV: out fp16 window layout
    gemm5<0><<<dim3(MQ / 128, HW / 128, NB), 512, SMEM_G>>>(
        wqf, bq, x, nullptr, qkv_buf, 576);

    // windowed cosine attention on window-native fp16
    attn4<<<dim3(NWIN, NH, NB), 128>>>(lscale);

    // proj + bias + residual -> fp32 output
    gemm5<1><<<dim3(MP / 128, HW / 128, NB), 512, SMEM_G>>>(
        wpf, bp, att_buf, x, out, 192);
}

// round 10
// speedup vs baseline: 5.1436x; 1.2754x over previous
#include <cuda_runtime.h>
#include <cuda_fp16.h>
#include <math.h>
#include <cstdint>

#define NH   8
#define HD   24
#define CDIM 192
#define HW   65536   // 256*256
#define NB   4
#define KDIM 192
#define MQ   640     // qkv rows padded to 5*128 (576 valid)
#define MP   256
#define NWIN 1024    // 32x32 windows

#define BPADH  136
#define APM 12288
// gemm6 smem layout (bytes):
//   A frags    @ 0      : 49152
//   B fp16 tile@ 49152  : 192*136*2 = 52224
//   B raw fp32 @ 101376 : 98304   (MODE 0 only)
#define SB_TILE 49152
#define SB_RAW  101376
#define SMEM_G0 199680
#define SMEM_G1 101376

// ---------------- device scratch (fp16 window-native intermediates) ----------------
__device__ __half   g_qkvh[(size_t)NB * NWIN * 576 * 64];   // (B, win, ch, tok)
__device__ __half   g_atth[(size_t)NB * NWIN * CDIM * 64];  // (B, win, ch, tok)
__device__ float    g_bias[NH * 64 * 64];
__device__ unsigned g_wqf[5 * APM];
__device__ unsigned g_wpf[2 * APM];
__device__ float    g_bq[MQ];
__device__ float    g_bp[MP];

// ---------------- helpers ----------------
__device__ __forceinline__ uint32_t smem_u32(const void* p) {
    uint32_t a;
    asm("{ .reg .u64 t; cvta.to.shared.u64 t, %1; cvt.u32.u64 %0, t; }" : "=r"(a) : "l"(p));
    return a;
}
__device__ __forceinline__ void cpa16(uint32_t dst, const void* src) {
    asm volatile("cp.async.cg.shared.global [%0], [%1], 16;" :: "r"(dst), "l"(src));
}
__device__ __forceinline__ void lds128(uint32_t* r, uint32_t a) {
    asm volatile("ld.shared.v4.b32 {%0,%1,%2,%3}, [%4];"
                 : "=r"(r[0]), "=r"(r[1]), "=r"(r[2]), "=r"(r[3]) : "r"(a));
}
__device__ __forceinline__ void ldmx4(uint32_t* r, uint32_t a) {
    asm volatile("ldmatrix.sync.aligned.m8n8.x4.shared.b16 {%0,%1,%2,%3}, [%4];"
                 : "=r"(r[0]), "=r"(r[1]), "=r"(r[2]), "=r"(r[3]) : "r"(a));
}
__device__ __forceinline__ void ldmx4t(uint32_t* r, uint32_t a) {
    asm volatile("ldmatrix.sync.aligned.m8n8.x4.trans.shared.b16 {%0,%1,%2,%3}, [%4];"
                 : "=r"(r[0]), "=r"(r[1]), "=r"(r[2]), "=r"(r[3]) : "r"(a));
}
__device__ __forceinline__ void ldmx2(uint32_t* r, uint32_t a) {
    asm volatile("ldmatrix.sync.aligned.m8n8.x2.shared.b16 {%0,%1}, [%2];"
                 : "=r"(r[0]), "=r"(r[1]) : "r"(a));
}
__device__ __forceinline__ void mma_f16(float* c, const uint32_t* a, const uint32_t* b) {
    asm volatile("mma.sync.aligned.m16n8k16.row.col.f32.f16.f16.f32 "
                 "{%0,%1,%2,%3}, {%4,%5,%6,%7}, {%8,%9}, {%0,%1,%2,%3};"
                 : "+f"(c[0]), "+f"(c[1]), "+f"(c[2]), "+f"(c[3])
                 : "r"(a[0]), "r"(a[1]), "r"(a[2]), "r"(a[3]), "r"(b[0]), "r"(b[1]));
}
__device__ __forceinline__ uint32_t pack_h2(float lo, float hi) {
    __half2 h = __floats2half2_rn(lo, hi);
    return *(uint32_t*)&h;
}

// ---------------- kernel 1: CPB bias table ----------------
__global__ void bias_kernel(const float* __restrict__ w1, const float* __restrict__ b1,
                            const float* __restrict__ w2)
{
    __shared__ float table[225][NH];
    int tid = threadIdx.x;

    if (tid < 225) {
        int a = tid / 15, b = tid % 15;
        const float inv_l8 = 1.0f / log2f(8.0f);
        float ca = (float)(a - 7) / 7.0f * 8.0f;
        float cb = (float)(b - 7) / 7.0f * 8.0f;
        float r0 = (ca == 0.f) ? 0.f : copysignf(log2f(fabsf(ca) + 1.0f) * inv_l8, ca);
        float r1 = (cb == 0.f) ? 0.f : copysignf(log2f(fabsf(cb) + 1.0f) * inv_l8, cb);
        float acc[NH];
        #pragma unroll
        for (int h = 0; h < NH; h++) acc[h] = 0.f;
        for (int j = 0; j < 512; j++) {
            float hv = fmaf(r0, w1[j], fmaf(r1, w1[512 + j], b1[j]));
            hv = fmaxf(hv, 0.f);
            #pragma unroll
            for (int h = 0; h < NH; h++) acc[h] = fmaf(hv, w2[j * NH + h], acc[h]);
        }
        #pragma unroll
        for (int h = 0; h < NH; h++) table[tid][h] = acc[h];
    }
    __syncthreads();

    for (int idx = tid; idx < NH * 64 * 64; idx += blockDim.x) {
        int h  = idx / (64 * 64);
        int nm = idx % (64 * 64);
        int n = nm / 64, m = nm % 64;
        int di = (n >> 3) - (m >> 3) + 7;
        int dj = (n & 7) - (m & 7) + 7;
        float t = table[di * 15 + dj][h];
        g_bias[idx] = 16.f / (1.f + expf(-t));
    }
}

// ---------------- kernel 1b: pack weights into fp16 m16n8k16 fragment layout ----------------
__global__ void prep_kernel(const float* __restrict__ qkv_w, const float* __restrict__ qb,
                            const float* __restrict__ vb,
                            const float* __restrict__ proj_w, const float* __restrict__ pb)
{
    int i = blockIdx.x * blockDim.x + threadIdx.x;
    int stride = gridDim.x * blockDim.x;

    for (int idx = i; idx < 5 * APM; idx += stride) {
        int mt  = idx / APM;
        int r   = idx % APM;
        int kst = r / 2048;
        int r2  = r % 2048;
        int slot = r2 & 3, lane = (r2 >> 2) & 31, mf = (r2 >> 7) & 7, ks = (r2 >> 10) & 1;
        int m = mt * 128 + mf * 16 + (lane >> 2) + (slot & 1) * 8;
        int k = kst * 32 + ks * 16 + (lane & 3) * 2 + ((slot >> 1) & 1) * 8;
        float v0 = (m < 576) ? qkv_w[m * KDIM + k]     : 0.f;
        float v1 = (m < 576) ? qkv_w[m * KDIM + k + 1] : 0.f;
        g_wqf[idx] = pack_h2(v0, v1);
    }
    for (int idx = i; idx < 2 * APM; idx += stride) {
        int mt  = idx / APM;
        int r   = idx % APM;
        int kst = r / 2048;
        int r2  = r % 2048;
        int slot = r2 & 3, lane = (r2 >> 2) & 31, mf = (r2 >> 7) & 7, ks = (r2 >> 10) & 1;
        int m = mt * 128 + mf * 16 + (lane >> 2) + (slot & 1) * 8;
        int k = kst * 32 + ks * 16 + (lane & 3) * 2 + ((slot >> 1) & 1) * 8;
        float v0 = (m < 192) ? proj_w[m * KDIM + k]     : 0.f;
        float v1 = (m < 192) ? proj_w[m * KDIM + k + 1] : 0.f;
        g_wpf[idx] = pack_h2(v0, v1);
    }
    if (i < MQ) {
        float v = 0.f;
        if (i < 192)                  v = qb[i];
        else if (i >= 384 && i < 576) v = vb[i - 384];
        g_bq[i] = v;
    }
    if (i < MP) g_bp[i] = (i < 192) ? pb[i] : 0.f;
}

// ---------------- kernel 2/4: single-shot K fp16 mma GEMM ----------------
// MODE 0 (QKV): B = fp32 X (pixel layout), out = fp16 window layout.
// MODE 1 (proj): B = fp16 g_atth (window layout), out = fp32 pixel layout + residual.
template<int MODE>
__global__ void __launch_bounds__(512) gemm6(
    const unsigned* __restrict__ Af,
    const float* __restrict__ bias,
    const void* __restrict__ Bsrc,
    const float* __restrict__ resid,
    void* __restrict__ outp,
    int Mvalid)
{
    extern __shared__ char sm[];
    const int tid = threadIdx.x;
    const int wid = tid >> 5, lane = tid & 31;
    const int wm = wid >> 2, wn = wid & 3;
    const int bz = blockIdx.z;
    const int m0 = blockIdx.x * 128;
    const int n0 = blockIdx.y * 128;
    const uint32_t sb = smem_u32(sm);

    const int py = n0 >> 8;

    // ---- issue ALL loads via cp.async ----
    {
        const char* Ag = (const char*)(Af + (size_t)blockIdx.x * APM);
        #pragma unroll
        for (int i = 0; i < 6; i++)
            cpa16(sb + (uint32_t)(i * 8192 + tid * 16), Ag + (i * 512 + tid) * 16);

        if (MODE == 0) {
            const float* Xb = (const float*)Bsrc + (size_t)bz * KDIM * HW + n0;
            #pragma unroll
            for (int i = 0; i < 12; i++) {
                int c = tid + i * 512;          // 0..6143
                int row = c >> 5, col16 = c & 31;
                cpa16(sb + SB_RAW + (uint32_t)c * 16,
                      Xb + (size_t)row * HW + col16 * 4);
            }
        } else {
            const __half* Bh = (const __half*)Bsrc;
            #pragma unroll
            for (int i = 0; i < 6; i++) {
                int c = tid + i * 512;          // 0..3071
                int row = c >> 4, g = c & 15;
                int px = (n0 & 255) + g * 8;
                int winb = ((py >> 3) << 5) + (px >> 3);
                int tok0 = (py & 7) * 8;
                cpa16(sb + SB_TILE + (uint32_t)(row * BPADH + g * 8) * 2,
                      Bh + ((size_t)(bz * NWIN + winb) * CDIM + row) * 64 + tok0);
            }
        }
        asm volatile("cp.async.commit_group;");
        asm volatile("cp.async.wait_group 0;" ::: "memory");
    }
    __syncthreads();

    // ---- MODE 0: convert raw fp32 B -> fp16 padded tile ----
    if (MODE == 0) {
        const float* raw = (const float*)(sm + SB_RAW);
        #pragma unroll
        for (int i = 0; i < 6; i++) {
            int j = tid + i * 512;              // 0..3071
            int row = j >> 4, col8 = (j & 15) * 8;
            float4 p0 = *(const float4*)(raw + row * 128 + col8);
            float4 p1 = *(const float4*)(raw + row * 128 + col8 + 4);
            uint4 t;
            t.x = pack_h2(p0.x, p0.y); t.y = pack_h2(p0.z, p0.w);
            t.z = pack_h2(p1.x, p1.y); t.w = pack_h2(p1.z, p1.w);
            *(uint4*)(sm + SB_TILE + (row * BPADH + col8) * 2) = t;
        }
        __syncthreads();
    }

    // ---- compute: 12 k-steps, no further syncs ----
    const int lrow = (lane & 7) + ((lane >> 3) & 1) * 8;
    const int lcol = ((lane >> 4) & 1) * 8;
    const uint32_t Bb = sb + SB_TILE + (uint32_t)((lrow * BPADH + wn * 32 + lcol) * 2);

    float acc[2][4][4];
    #pragma unroll
    for (int mf = 0; mf < 2; mf++)
        #pragma unroll
        for (int nf = 0; nf < 4; nf++)
            #pragma unroll
            for (int j = 0; j < 4; j++) acc[mf][nf][j] = 0.f;

    #pragma unroll
    for (int kk = 0; kk < 12; kk++) {
        uint32_t a[2][4];
        const uint32_t Ab = sb + (kk >> 1) * 8192;
        lds128(a[0], Ab + (((kk & 1) * 8 + wm * 2 + 0) * 32 + lane) * 16);
        lds128(a[1], Ab + (((kk & 1) * 8 + wm * 2 + 1) * 32 + lane) * 16);
        uint32_t bm[2][4];
        #pragma unroll
        for (int nfp = 0; nfp < 2; nfp++)
            ldmx4t(bm[nfp], Bb + (uint32_t)((kk * 16 * BPADH + nfp * 16) * 2));
        #pragma unroll
        for (int mf = 0; mf < 2; mf++)
            #pragma unroll
            for (int nf = 0; nf < 4; nf++)
                mma_f16(acc[mf][nf], a[mf], &bm[nf >> 1][(nf & 1) * 2]);
    }

    // ---- epilogue ----
    const int gr = lane >> 2;
    const int qc = (lane & 3) * 2;

    if (MODE == 0) {
        int win[4], tok[4];
        #pragma unroll
        for (int nf = 0; nf < 4; nf++) {
            int px = (n0 & 255) + wn * 32 + nf * 8 + qc;
            win[nf] = ((py >> 3) << 5) + (px >> 3);
            tok[nf] = (py & 7) * 8 + (px & 7);
        }
        __half* outW = (__half*)outp + (size_t)bz * NWIN * 576 * 64;
        #pragma unroll
        for (int mf = 0; mf < 2; mf++) {
            #pragma unroll
            for (int hh = 0; hh < 2; hh++) {
                int m = m0 + wm * 32 + mf * 16 + gr + hh * 8;
                if (m < Mvalid) {
                    float bv = bias[m];
                    #pragma unroll
                    for (int nf = 0; nf < 4; nf++) {
                        __half2 o = __floats2half2_rn(acc[mf][nf][hh * 2 + 0] + bv,
                                                      acc[mf][nf][hh * 2 + 1] + bv);
                        *(__half2*)&outW[((size_t)win[nf] * 576 + m) * 64 + tok[nf]] = o;
                    }
                }
            }
        }
    } else {
        float* outB = (float*)outp + (size_t)bz * CDIM * HW;
        const float* resB = resid + (size_t)bz * CDIM * HW;
        #pragma unroll
        for (int mf = 0; mf < 2; mf++) {
            #pragma unroll
            for (int hh = 0; hh < 2; hh++) {
                int m = m0 + wm * 32 + mf * 16 + gr + hh * 8;
                if (m < Mvalid) {
                    float bv = bias[m];
                    float* orow = outB + (size_t)m * HW + n0 + wn * 32 + qc;
                    const float* rrow = resB + (size_t)m * HW + n0 + wn * 32 + qc;
                    #pragma unroll
                    for (int nf = 0; nf < 4; nf++) {
                        float2 o;
                        o.x = acc[mf][nf][hh * 2 + 0] + bv;
                        o.y = acc[mf][nf][hh * 2 + 1] + bv;
                        float2 rv = *(const float2*)(rrow + nf * 8);
                        o.x += rv.x; o.y += rv.y;
                        *(float2*)(orow + nf * 8) = o;
                    }
                }
            }
        }
    }
}

// ---------------- kernel 3: tensor-core attention on window-native fp16 (R9, proven) ----------------
__global__ void __launch_bounds__(128) attn4(const float* __restrict__ logit_scale)
{
    __shared__ __half qs_[32 * 72];
    __shared__ __half ks_[32 * 72];
    __shared__ __half vs_[24 * 72];
    __shared__ __half os_[24 * 72];
    __shared__ float qn[64], kn[64];

    const int tid  = threadIdx.x;
    const int lane = tid & 31;
    const int wr   = tid >> 5;
    const int win  = blockIdx.x;
    const int h    = blockIdx.y;
    const int bz   = blockIdx.z;

    const float LN100 = 4.6051701860f;
    const float scale_h = expf(fminf(logit_scale[h], LN100));

    const __half* gq = g_qkvh + ((size_t)(bz * NWIN + win) * 576 + h * HD) * 64;
    #pragma unroll
    for (int pass = 0; pass < 5; pass++) {
        int idx = tid + pass * 128;
        if (idx < 576) {
            int arr = idx / 192, rem = idx % 192;
            int d = rem >> 3, tg = rem & 7;
            uint4 val = *(const uint4*)(gq + (size_t)arr * 192 * 64 + d * 64 + tg * 8);
            __half* dst = (arr == 0) ? qs_ : (arr == 1) ? ks_ : vs_;
            *(uint4*)&dst[d * 72 + tg * 8] = val;
        }
    }
    {
        int arr2 = tid >> 6, rr = (tid >> 3) & 7, tg = tid & 7;
        __half* dst = arr2 ? ks_ : qs_;
        *(uint4*)&dst[(24 + rr) * 72 + tg * 8] = make_uint4(0, 0, 0, 0);
    }
    __syncthreads();

    {
        int t = tid & 63;
        const __half* col = (tid < 64) ? qs_ : ks_;
        float ss = 0.f;
        #pragma unroll
        for (int d = 0; d < HD; d++) {
            float f = __half2float(col[d * 72 + t]);
            ss = fmaf(f, f, ss);
        }
        float inv = 1.f / fmaxf(sqrtf(ss), 1e-12f);
        if (tid < 64) qn[t] = inv * scale_h; else kn[t] = inv;
    }
    __syncthreads();

    const uint32_t qb = smem_u32(qs_), kb = smem_u32(ks_), vb = smem_u32(vs_);
    const int gr = lane >> 2;
    const int qc = (lane & 3) * 2;
    const int r0 = wr * 16 + gr, r1 = r0 + 8;

    float S[8][4];
    #pragma unroll
    for (int nb = 0; nb < 8; nb++)
        #pragma unroll
        for (int j = 0; j < 4; j++) S[nb][j] = 0.f;

    #pragma unroll
    for (int ks = 0; ks < 2; ks++) {
        uint32_t a[4];
        ldmx4t(a, qb + (uint32_t)(((ks * 16 + (lane & 7) + ((lane >> 4) & 1) * 8) * 72
                                   + wr * 16 + ((lane >> 3) & 1) * 8) * 2));
        #pragma unroll
        for (int nbp = 0; nbp < 4; nbp++) {
            uint32_t b[4];
            ldmx4t(b, kb + (uint32_t)(((ks * 16 + (lane & 7) + ((lane >> 3) & 1) * 8) * 72
                                       + nbp * 16 + ((lane >> 4) & 1) * 8) * 2));
            mma_f16(S[nbp * 2],     a, &b[0]);
            mma_f16(S[nbp * 2 + 1], a, &b[2]);
        }
    }

    const float qn0 = qn[r0], qn1 = qn[r1];
    #pragma unroll
    for (int nb = 0; nb < 8; nb++) {
        int c0 = nb * 8 + qc;
        float k0v = kn[c0], k1v = kn[c0 + 1];
        float2 b0 = *(const float2*)&g_bias[(h * 64 + r0) * 64 + c0];
        float2 b1 = *(const float2*)&g_bias[(h * 64 + r1) * 64 + c0];
        S[nb][0] = S[nb][0] * qn0 * k0v + b0.x;
        S[nb][1] = S[nb][1] * qn0 * k1v + b0.y;
        S[nb][2] = S[nb][2] * qn1 * k0v + b1.x;
        S[nb][3] = S[nb][3] * qn1 * k1v + b1.y;
    }

    float mx0 = -1e30f, mx1 = -1e30f;
    #pragma unroll
    for (int nb = 0; nb < 8; nb++) {
        mx0 = fmaxf(mx0, fmaxf(S[nb][0], S[nb][1]));
        mx1 = fmaxf(mx1, fmaxf(S[nb][2], S[nb][3]));
    }
    mx0 = fmaxf(mx0, __shfl_xor_sync(0xffffffffu, mx0, 1));
    mx0 = fmaxf(mx0, __shfl_xor_sync(0xffffffffu, mx0, 2));
    mx1 = fmaxf(mx1, __shfl_xor_sync(0xffffffffu, mx1, 1));
    mx1 = fmaxf(mx1, __shfl_xor_sync(0xffffffffu, mx1, 2));
    float s0 = 0.f, s1 = 0.f;
    #pragma unroll
    for (int nb = 0; nb < 8; nb++) {
        S[nb][0] = __expf(S[nb][0] - mx0); s0 += S[nb][0];
        S[nb][1] = __expf(S[nb][1] - mx0); s0 += S[nb][1];
        S[nb][2] = __expf(S[nb][2] - mx1); s1 += S[nb][2];
        S[nb][3] = __expf(S[nb][3] - mx1); s1 += S[nb][3];
    }
    s0 += __shfl_xor_sync(0xffffffffu, s0, 1);
    s0 += __shfl_xor_sync(0xffffffffu, s0, 2);
    s1 += __shfl_xor_sync(0xffffffffu, s1, 1);
    s1 += __shfl_xor_sync(0xffffffffu, s1, 2);
    float pinv0 = 1.f / s0, pinv1 = 1.f / s1;
    #pragma unroll
    for (int nb = 0; nb < 8; nb++) {
        S[nb][0] *= pinv0; S[nb][1] *= pinv0;
        S[nb][2] *= pinv1; S[nb][3] *= pinv1;
    }

    float O[3][4];
    #pragma unroll
    for (int nb3 = 0; nb3 < 3; nb3++)
        #pragma unroll
        for (int j = 0; j < 4; j++) O[nb3][j] = 0.f;

    #pragma unroll
    for (int kt = 0; kt < 4; kt++) {
        uint32_t a[4];
        a[0] = pack_h2(S[2 * kt][0],     S[2 * kt][1]);
        a[1] = pack_h2(S[2 * kt][2],     S[2 * kt][3]);
        a[2] = pack_h2(S[2 * kt + 1][0], S[2 * kt + 1][1]);
        a[3] = pack_h2(S[2 * kt + 1][2], S[2 * kt + 1][3]);
        uint32_t b[4];
        ldmx4(b, vb + (uint32_t)((((lane & 7) + ((lane >> 4) & 1) * 8) * 72
                                   + kt * 16 + ((lane >> 3) & 1) * 8) * 2));
        mma_f16(O[0], a, &b[0]);
        mma_f16(O[1], a, &b[2]);
        uint32_t b2[2];
        ldmx2(b2, vb + (uint32_t)(((16 + (lane & 7)) * 72
                                    + kt * 16 + (((lane & 15) >> 3) & 1) * 8) * 2));
        mma_f16(O[2], a, b2);
    }

    #pragma unroll
    for (int nb3 = 0; nb3 < 3; nb3++) {
        int d = nb3 * 8 + qc;
        os_[d * 72 + r0]       = __float2half(O[nb3][0]);
        os_[(d + 1) * 72 + r0] = __float2half(O[nb3][1]);
        os_[d * 72 + r1]       = __float2half(O[nb3][2]);
        os_[(d + 1) * 72 + r1] = __float2half(O[nb3][3]);
    }
    __syncthreads();

    __half* ga = g_atth + ((size_t)(bz * NWIN + win) * CDIM + h * HD) * 64;
    #pragma unroll
    for (int pass = 0; pass < 2; pass++) {
        int idx = tid + pass * 128;
        if (idx < 192) {
            int d = idx >> 3, tg = idx & 7;
            *(uint4*)(ga + d * 64 + tg * 8) = *(uint4*)&os_[d * 72 + tg * 8];
        }
    }
}

// ---------------- launch ----------------
extern "C" void kernel_launch(void* const* d_in, const int* in_sizes, int n_in,
                              void* d_out, int out_size)
{
    const float* x        = (const float*)d_in[0];
    const float* qkv_w    = (const float*)d_in[2];
    const float* q_bias   = (const float*)d_in[3];
    const float* v_bias   = (const float*)d_in[4];
    const float* lscale   = (const float*)d_in[5];
    const float* cpb_w1   = (const float*)d_in[6];
    const float* cpb_b1   = (const float*)d_in[7];
    const float* cpb_w2   = (const float*)d_in[8];
    const float* proj_w   = (const float*)d_in[9];
    const float* proj_b   = (const float*)d_in[10];
    float* out = (float*)d_out;

    __half *qkv_buf, *att_buf;
    float *bq, *bp;
    unsigned *wqf, *wpf;
    cudaGetSymbolAddress((void**)&qkv_buf, g_qkvh);
    cudaGetSymbolAddress((void**)&att_buf, g_atth);
    cudaGetSymbolAddress((void**)&wqf, g_wqf);
    cudaGetSymbolAddress((void**)&wpf, g_wpf);
    cudaGetSymbolAddress((void**)&bq, g_bq);
    cudaGetSymbolAddress((void**)&bp, g_bp);

    cudaFuncSetAttribute(gemm6<0>, cudaFuncAttributeMaxDynamicSharedMemorySize, SMEM_G0);
    cudaFuncSetAttribute(gemm6<1>, cudaFuncAttributeMaxDynamicSharedMemorySize, SMEM_G1);

    bias_kernel<<<1, 256>>>(cpb_w1, cpb_b1, cpb_w2);
    prep_kernel<<<128, 256>>>(qkv_w, q_bias, v_bias, proj_w, proj_b);

    // QKV: fp16 window-layout output
    gemm6<0><<<dim3(MQ / 128, HW / 128, NB), 512, SMEM_G0>>>(
        wqf, bq, x, nullptr, qkv_buf, 576);

    // windowed cosine attention on window-native fp16
    attn4<<<dim3(NWIN, NH, NB), 128>>>(lscale);

    // proj + bias + residual -> fp32 output
    gemm6<1><<<dim3(MP / 128, HW / 128, NB), 512, SMEM_G1>>>(
        wpf, bp, att_buf, x, out, 192);
}

// round 11
// speedup vs baseline: 5.8089x; 1.1294x over previous
#include <cuda_runtime.h>
#include <cuda_fp16.h>
#include <math.h>
#include <cstdint>

#define NH   8
#define HD   24
#define CDIM 192
#define HW   65536   // 256*256
#define NB   4
#define KDIM 192
#define MQ   640     // qkv rows padded to 5*128 (576 valid)
#define MP   256
#define NWIN 1024    // 32x32 windows

#define BPADH  136
#define APM 12288
// gemm7 smem (bytes): A frags @0 : 49152 ; B fp16 tile @49152 : 192*136*2 = 52224
#define SB_TILE 49152
#define SMEM_G  101376

// ---------------- device scratch (fp16 window-native intermediates) ----------------
__device__ __half   g_qkvh[(size_t)NB * NWIN * 576 * 64];   // (B, win, ch, tok)
__device__ __half   g_atth[(size_t)NB * NWIN * CDIM * 64];  // (B, win, ch, tok)
__device__ float    g_bias[NH * 64 * 64];
__device__ unsigned g_wqf[5 * APM];
__device__ unsigned g_wpf[2 * APM];
__device__ float    g_bq[MQ];
__device__ float    g_bp[MP];

// ---------------- helpers ----------------
__device__ __forceinline__ uint32_t smem_u32(const void* p) {
    uint32_t a;
    asm("{ .reg .u64 t; cvta.to.shared.u64 t, %1; cvt.u32.u64 %0, t; }" : "=r"(a) : "l"(p));
    return a;
}
__device__ __forceinline__ void cpa16(uint32_t dst, const void* src) {
    asm volatile("cp.async.cg.shared.global [%0], [%1], 16;" :: "r"(dst), "l"(src));
}
__device__ __forceinline__ void lds128(uint32_t* r, uint32_t a) {
    asm volatile("ld.shared.v4.b32 {%0,%1,%2,%3}, [%4];"
                 : "=r"(r[0]), "=r"(r[1]), "=r"(r[2]), "=r"(r[3]) : "r"(a));
}
__device__ __forceinline__ void ldmx4(uint32_t* r, uint32_t a) {
    asm volatile("ldmatrix.sync.aligned.m8n8.x4.shared.b16 {%0,%1,%2,%3}, [%4];"
                 : "=r"(r[0]), "=r"(r[1]), "=r"(r[2]), "=r"(r[3]) : "r"(a));
}
__device__ __forceinline__ void ldmx4t(uint32_t* r, uint32_t a) {
    asm volatile("ldmatrix.sync.aligned.m8n8.x4.trans.shared.b16 {%0,%1,%2,%3}, [%4];"
                 : "=r"(r[0]), "=r"(r[1]), "=r"(r[2]), "=r"(r[3]) : "r"(a));
}
__device__ __forceinline__ void ldmx2(uint32_t* r, uint32_t a) {
    asm volatile("ldmatrix.sync.aligned.m8n8.x2.shared.b16 {%0,%1}, [%2];"
                 : "=r"(r[0]), "=r"(r[1]) : "r"(a));
}
__device__ __forceinline__ void mma_f16(float* c, const uint32_t* a, const uint32_t* b) {
    asm volatile("mma.sync.aligned.m16n8k16.row.col.f32.f16.f16.f32 "
                 "{%0,%1,%2,%3}, {%4,%5,%6,%7}, {%8,%9}, {%0,%1,%2,%3};"
                 : "+f"(c[0]), "+f"(c[1]), "+f"(c[2]), "+f"(c[3])
                 : "r"(a[0]), "r"(a[1]), "r"(a[2]), "r"(a[3]), "r"(b[0]), "r"(b[1]));
}
__device__ __forceinline__ uint32_t pack_h2(float lo, float hi) {
    __half2 h = __floats2half2_rn(lo, hi);
    return *(uint32_t*)&h;
}

// ---------------- kernel 1: CPB bias table ----------------
__global__ void bias_kernel(const float* __restrict__ w1, const float* __restrict__ b1,
                            const float* __restrict__ w2)
{
    __shared__ float table[225][NH];
    int tid = threadIdx.x;

    if (tid < 225) {
        int a = tid / 15, b = tid % 15;
        const float inv_l8 = 1.0f / log2f(8.0f);
        float ca = (float)(a - 7) / 7.0f * 8.0f;
        float cb = (float)(b - 7) / 7.0f * 8.0f;
        float r0 = (ca == 0.f) ? 0.f : copysignf(log2f(fabsf(ca) + 1.0f) * inv_l8, ca);
        float r1 = (cb == 0.f) ? 0.f : copysignf(log2f(fabsf(cb) + 1.0f) * inv_l8, cb);
        float acc[NH];
        #pragma unroll
        for (int h = 0; h < NH; h++) acc[h] = 0.f;
        for (int j = 0; j < 512; j++) {
            float hv = fmaf(r0, w1[j], fmaf(r1, w1[512 + j], b1[j]));
            hv = fmaxf(hv, 0.f);
            #pragma unroll
            for (int h = 0; h < NH; h++) acc[h] = fmaf(hv, w2[j * NH + h], acc[h]);
        }
        #pragma unroll
        for (int h = 0; h < NH; h++) table[tid][h] = acc[h];
    }
    __syncthreads();

    for (int idx = tid; idx < NH * 64 * 64; idx += blockDim.x) {
        int h  = idx / (64 * 64);
        int nm = idx % (64 * 64);
        int n = nm / 64, m = nm % 64;
        int di = (n >> 3) - (m >> 3) + 7;
        int dj = (n & 7) - (m & 7) + 7;
        float t = table[di * 15 + dj][h];
        g_bias[idx] = 16.f / (1.f + expf(-t));
    }
}

// ---------------- kernel 1b: pack weights into fp16 m16n8k16 fragment layout ----------------
__global__ void prep_kernel(const float* __restrict__ qkv_w, const float* __restrict__ qb,
                            const float* __restrict__ vb,
                            const float* __restrict__ proj_w, const float* __restrict__ pb)
{
    int i = blockIdx.x * blockDim.x + threadIdx.x;
    int stride = gridDim.x * blockDim.x;

    for (int idx = i; idx < 5 * APM; idx += stride) {
        int mt  = idx / APM;
        int r   = idx % APM;
        int kst = r / 2048;
        int r2  = r % 2048;
        int slot = r2 & 3, lane = (r2 >> 2) & 31, mf = (r2 >> 7) & 7, ks = (r2 >> 10) & 1;
        int m = mt * 128 + mf * 16 + (lane >> 2) + (slot & 1) * 8;
        int k = kst * 32 + ks * 16 + (lane & 3) * 2 + ((slot >> 1) & 1) * 8;
        float v0 = (m < 576) ? qkv_w[m * KDIM + k]     : 0.f;
        float v1 = (m < 576) ? qkv_w[m * KDIM + k + 1] : 0.f;
        g_wqf[idx] = pack_h2(v0, v1);
    }
    for (int idx = i; idx < 2 * APM; idx += stride) {
        int mt  = idx / APM;
        int r   = idx % APM;
        int kst = r / 2048;
        int r2  = r % 2048;
        int slot = r2 & 3, lane = (r2 >> 2) & 31, mf = (r2 >> 7) & 7, ks = (r2 >> 10) & 1;
        int m = mt * 128 + mf * 16 + (lane >> 2) + (slot & 1) * 8;
        int k = kst * 32 + ks * 16 + (lane & 3) * 2 + ((slot >> 1) & 1) * 8;
        float v0 = (m < 192) ? proj_w[m * KDIM + k]     : 0.f;
        float v1 = (m < 192) ? proj_w[m * KDIM + k + 1] : 0.f;
        g_wpf[idx] = pack_h2(v0, v1);
    }
    if (i < MQ) {
        float v = 0.f;
        if (i < 192)                  v = qb[i];
        else if (i >= 384 && i < 576) v = vb[i - 384];
        g_bq[i] = v;
    }
    if (i < MP) g_bp[i] = (i < 192) ? pb[i] : 0.f;
}

// ---------------- kernel 2/4: single-shot K fp16 mma GEMM, 2 CTA/SM ----------------
// 256 threads (8 warps: wm=wid>>1 in 0..3, wn=wid&1 in 0..1), warp tile 32x64.
// MODE 0 (QKV): B = fp32 X (pixel layout) via LDG+cvt+STS; out = fp16 window layout.
// MODE 1 (proj): B = fp16 g_atth via cp.async; out = fp32 pixel layout + residual.
template<int MODE>
__global__ void __launch_bounds__(256, 2) gemm7(
    const unsigned* __restrict__ Af,
    const float* __restrict__ bias,
    const void* __restrict__ Bsrc,
    const float* __restrict__ resid,
    void* __restrict__ outp,
    int Mvalid)
{
    extern __shared__ char sm[];
    const int tid = threadIdx.x;
    const int wid = tid >> 5, lane = tid & 31;
    const int wm = wid >> 1, wn = wid & 1;
    const int bz = blockIdx.z;
    const int m0 = blockIdx.x * 128;
    const int n0 = blockIdx.y * 128;
    const uint32_t sb = smem_u32(sm);

    const int py = n0 >> 8;

    // ---- A via cp.async (12 chunks/thread) ----
    {
        const char* Ag = (const char*)(Af + (size_t)blockIdx.x * APM);
        #pragma unroll
        for (int i = 0; i < 12; i++)
            cpa16(sb + (uint32_t)((i * 256 + tid) * 16), Ag + (i * 256 + tid) * 16);
        if (MODE == 1) {
            const __half* Bh = (const __half*)Bsrc;
            #pragma unroll
            for (int i = 0; i < 12; i++) {
                int c = tid + i * 256;          // 0..3071
                int row = c >> 4, g = c & 15;
                int px = (n0 & 255) + g * 8;
                int winb = ((py >> 3) << 5) + (px >> 3);
                int tok0 = (py & 7) * 8;
                cpa16(sb + SB_TILE + (uint32_t)(row * BPADH + g * 8) * 2,
                      Bh + ((size_t)(bz * NWIN + winb) * CDIM + row) * 64 + tok0);
            }
        }
        asm volatile("cp.async.commit_group;");
    }

    // ---- MODE 0: B fp32 LDG -> cvt -> STS (overlaps the other CTA's compute) ----
    if (MODE == 0) {
        const float* Xb = (const float*)Bsrc + (size_t)bz * KDIM * HW + n0;
        #pragma unroll
        for (int i = 0; i < 12; i++) {
            int c = tid + i * 256;              // 0..3071
            int row = c >> 4, col8 = (c & 15) * 8;
            const float* src = Xb + (size_t)row * HW + col8;
            float4 p0 = *(const float4*)src;
            float4 p1 = *(const float4*)(src + 4);
            uint4 t;
            t.x = pack_h2(p0.x, p0.y); t.y = pack_h2(p0.z, p0.w);
            t.z = pack_h2(p1.x, p1.y); t.w = pack_h2(p1.z, p1.w);
            *(uint4*)(sm + SB_TILE + (row * BPADH + col8) * 2) = t;
        }
    }

    asm volatile("cp.async.wait_group 0;" ::: "memory");
    __syncthreads();

    // ---- compute: 12 k-steps, no further syncs ----
    const int lrow = (lane & 7) + ((lane >> 3) & 1) * 8;
    const int lcol = ((lane >> 4) & 1) * 8;
    const uint32_t Bb = sb + SB_TILE + (uint32_t)((lrow * BPADH + wn * 64 + lcol) * 2);

    float acc[2][8][4];
    #pragma unroll
    for (int mf = 0; mf < 2; mf++)
        #pragma unroll
        for (int nf = 0; nf < 8; nf++)
            #pragma unroll
            for (int j = 0; j < 4; j++) acc[mf][nf][j] = 0.f;

    #pragma unroll
    for (int kk = 0; kk < 12; kk++) {
        uint32_t a[2][4];
        const uint32_t Ab = sb + (kk >> 1) * 8192;
        lds128(a[0], Ab + (((kk & 1) * 8 + wm * 2 + 0) * 32 + lane) * 16);
        lds128(a[1], Ab + (((kk & 1) * 8 + wm * 2 + 1) * 32 + lane) * 16);
        uint32_t bm[4][4];
        #pragma unroll
        for (int nfp = 0; nfp < 4; nfp++)
            ldmx4t(bm[nfp], Bb + (uint32_t)((kk * 16 * BPADH + nfp * 16) * 2));
        #pragma unroll
        for (int mf = 0; mf < 2; mf++)
            #pragma unroll
            for (int nf = 0; nf < 8; nf++)
                mma_f16(acc[mf][nf], a[mf], &bm[nf >> 1][(nf & 1) * 2]);
    }

    // ---- epilogue ----
    const int gr = lane >> 2;
    const int qc = (lane & 3) * 2;

    if (MODE == 0) {
        __half* outW = (__half*)outp + (size_t)bz * NWIN * 576 * 64;
        #pragma unroll
        for (int mf = 0; mf < 2; mf++) {
            #pragma unroll
            for (int hh = 0; hh < 2; hh++) {
                int m = m0 + wm * 32 + mf * 16 + gr + hh * 8;
                if (m < Mvalid) {
                    float bv = bias[m];
                    #pragma unroll
                    for (int nf = 0; nf < 8; nf++) {
                        int px = (n0 & 255) + wn * 64 + nf * 8 + qc;
                        int win = ((py >> 3) << 5) + (px >> 3);
                        int tok = (py & 7) * 8 + (px & 7);
                        __half2 o = __floats2half2_rn(acc[mf][nf][hh * 2 + 0] + bv,
                                                      acc[mf][nf][hh * 2 + 1] + bv);
                        *(__half2*)&outW[((size_t)win * 576 + m) * 64 + tok] = o;
                    }
                }
            }
        }
    } else {
        float* outB = (float*)outp + (size_t)bz * CDIM * HW;
        const float* resB = resid + (size_t)bz * CDIM * HW;
        #pragma unroll
        for (int mf = 0; mf < 2; mf++) {
            #pragma unroll
            for (int hh = 0; hh < 2; hh++) {
                int m = m0 + wm * 32 + mf * 16 + gr + hh * 8;
                if (m < Mvalid) {
                    float bv = bias[m];
                    float* orow = outB + (size_t)m * HW + n0 + wn * 64 + qc;
                    const float* rrow = resB + (size_t)m * HW + n0 + wn * 64 + qc;
                    #pragma unroll
                    for (int nf = 0; nf < 8; nf++) {
                        float2 o;
                        o.x = acc[mf][nf][hh * 2 + 0] + bv;
                        o.y = acc[mf][nf][hh * 2 + 1] + bv;
                        float2 rv = *(const float2*)(rrow + nf * 8);
                        o.x += rv.x; o.y += rv.y;
                        *(float2*)(orow + nf * 8) = o;
                    }
                }
            }
        }
    }
}

// ---------------- kernel 3: tensor-core attention on window-native fp16 (R9, proven) ----------------
__global__ void __launch_bounds__(128) attn4(const float* __restrict__ logit_scale)
{
    __shared__ __half qs_[32 * 72];
    __shared__ __half ks_[32 * 72];
    __shared__ __half vs_[24 * 72];
    __shared__ __half os_[24 * 72];
    __shared__ float qn[64], kn[64];

    const int tid  = threadIdx.x;
    const int lane = tid & 31;
    const int wr   = tid >> 5;
    const int win  = blockIdx.x;
    const int h    = blockIdx.y;
    const int bz   = blockIdx.z;

    const float LN100 = 4.6051701860f;
    const float scale_h = expf(fminf(logit_scale[h], LN100));

    const __half* gq = g_qkvh + ((size_t)(bz * NWIN + win) * 576 + h * HD) * 64;
    #pragma unroll
    for (int pass = 0; pass < 5; pass++) {
        int idx = tid + pass * 128;
        if (idx < 576) {
            int arr = idx / 192, rem = idx % 192;
            int d = rem >> 3, tg = rem & 7;
            uint4 val = *(const uint4*)(gq + (size_t)arr * 192 * 64 + d * 64 + tg * 8);
            __half* dst = (arr == 0) ? qs_ : (arr == 1) ? ks_ : vs_;
            *(uint4*)&dst[d * 72 + tg * 8] = val;
        }
    }
    {
        int arr2 = tid >> 6, rr = (tid >> 3) & 7, tg = tid & 7;
        __half* dst = arr2 ? ks_ : qs_;
        *(uint4*)&dst[(24 + rr) * 72 + tg * 8] = make_uint4(0, 0, 0, 0);
    }
    __syncthreads();

    {
        int t = tid & 63;
        const __half* col = (tid < 64) ? qs_ : ks_;
        float ss = 0.f;
        #pragma unroll
        for (int d = 0; d < HD; d++) {
            float f = __half2float(col[d * 72 + t]);
            ss = fmaf(f, f, ss);
        }
        float inv = 1.f / fmaxf(sqrtf(ss), 1e-12f);
        if (tid < 64) qn[t] = inv * scale_h; else kn[t] = inv;
    }
    __syncthreads();

    const uint32_t qb = smem_u32(qs_), kb = smem_u32(ks_), vb = smem_u32(vs_);
    const int gr = lane >> 2;
    const int qc = (lane & 3) * 2;
    const int r0 = wr * 16 + gr, r1 = r0 + 8;

    float S[8][4];
    #pragma unroll
    for (int nb = 0; nb < 8; nb++)
        #pragma unroll
        for (int j = 0; j < 4; j++) S[nb][j] = 0.f;

    #pragma unroll
    for (int ks = 0; ks < 2; ks++) {
        uint32_t a[4];
        ldmx4t(a, qb + (uint32_t)(((ks * 16 + (lane & 7) + ((lane >> 4) & 1) * 8) * 72
                                   + wr * 16 + ((lane >> 3) & 1) * 8) * 2));
        #pragma unroll
        for (int nbp = 0; nbp < 4; nbp++) {
            uint32_t b[4];
            ldmx4t(b, kb + (uint32_t)(((ks * 16 + (lane & 7) + ((lane >> 3) & 1) * 8) * 72
                                       + nbp * 16 + ((lane >> 4) & 1) * 8) * 2));
            mma_f16(S[nbp * 2],     a, &b[0]);
            mma_f16(S[nbp * 2 + 1], a, &b[2]);
        }
    }

    const float qn0 = qn[r0], qn1 = qn[r1];
    #pragma unroll
    for (int nb = 0; nb < 8; nb++) {
        int c0 = nb * 8 + qc;
        float k0v = kn[c0], k1v = kn[c0 + 1];
        float2 b0 = *(const float2*)&g_bias[(h * 64 + r0) * 64 + c0];
        float2 b1 = *(const float2*)&g_bias[(h * 64 + r1) * 64 + c0];
        S[nb][0] = S[nb][0] * qn0 * k0v + b0.x;
        S[nb][1] = S[nb][1] * qn0 * k1v + b0.y;
        S[nb][2] = S[nb][2] * qn1 * k0v + b1.x;
        S[nb][3] = S[nb][3] * qn1 * k1v + b1.y;
    }

    float mx0 = -1e30f, mx1 = -1e30f;
    #pragma unroll
    for (int nb = 0; nb < 8; nb++) {
        mx0 = fmaxf(mx0, fmaxf(S[nb][0], S[nb][1]));
        mx1 = fmaxf(mx1, fmaxf(S[nb][2], S[nb][3]));
    }
    mx0 = fmaxf(mx0, __shfl_xor_sync(0xffffffffu, mx0, 1));
    mx0 = fmaxf(mx0, __shfl_xor_sync(0xffffffffu, mx0, 2));
    mx1 = fmaxf(mx1, __shfl_xor_sync(0xffffffffu, mx1, 1));
    mx1 = fmaxf(mx1, __shfl_xor_sync(0xffffffffu, mx1, 2));
    float s0 = 0.f, s1 = 0.f;
    #pragma unroll
    for (int nb = 0; nb < 8; nb++) {
        S[nb][0] = __expf(S[nb][0] - mx0); s0 += S[nb][0];
        S[nb][1] = __expf(S[nb][1] - mx0); s0 += S[nb][1];
        S[nb][2] = __expf(S[nb][2] - mx1); s1 += S[nb][2];
        S[nb][3] = __expf(S[nb][3] - mx1); s1 += S[nb][3];
    }
    s0 += __shfl_xor_sync(0xffffffffu, s0, 1);
    s0 += __shfl_xor_sync(0xffffffffu, s0, 2);
    s1 += __shfl_xor_sync(0xffffffffu, s1, 1);
    s1 += __shfl_xor_sync(0xffffffffu, s1, 2);
    float pinv0 = 1.f / s0, pinv1 = 1.f / s1;
    #pragma unroll
    for (int nb = 0; nb < 8; nb++) {
        S[nb][0] *= pinv0; S[nb][1] *= pinv0;
        S[nb][2] *= pinv1; S[nb][3] *= pinv1;
    }

    float O[3][4];
    #pragma unroll
    for (int nb3 = 0; nb3 < 3; nb3++)
        #pragma unroll
        for (int j = 0; j < 4; j++) O[nb3][j] = 0.f;

    #pragma unroll
    for (int kt = 0; kt < 4; kt++) {
        uint32_t a[4];
        a[0] = pack_h2(S[2 * kt][0],     S[2 * kt][1]);
        a[1] = pack_h2(S[2 * kt][2],     S[2 * kt][3]);
        a[2] = pack_h2(S[2 * kt + 1][0], S[2 * kt + 1][1]);
        a[3] = pack_h2(S[2 * kt + 1][2], S[2 * kt + 1][3]);
        uint32_t b[4];
        ldmx4(b, vb + (uint32_t)((((lane & 7) + ((lane >> 4) & 1) * 8) * 72
                                   + kt * 16 + ((lane >> 3) & 1) * 8) * 2));
        mma_f16(O[0], a, &b[0]);
        mma_f16(O[1], a, &b[2]);
        uint32_t b2[2];
        ldmx2(b2, vb + (uint32_t)(((16 + (lane & 7)) * 72
                                    + kt * 16 + (((lane & 15) >> 3) & 1) * 8) * 2));
        mma_f16(O[2], a, b2);
    }

    #pragma unroll
    for (int nb3 = 0; nb3 < 3; nb3++) {
        int d = nb3 * 8 + qc;
        os_[d * 72 + r0]       = __float2half(O[nb3][0]);
        os_[(d + 1) * 72 + r0] = __float2half(O[nb3][1]);
        os_[d * 72 + r1]       = __float2half(O[nb3][2]);
        os_[(d + 1) * 72 + r1] = __float2half(O[nb3][3]);
    }
    __syncthreads();

    __half* ga = g_atth + ((size_t)(bz * NWIN + win) * CDIM + h * HD) * 64;
    #pragma unroll
    for (int pass = 0; pass < 2; pass++) {
        int idx = tid + pass * 128;
        if (idx < 192) {
            int d = idx >> 3, tg = idx & 7;
            *(uint4*)(ga + d * 64 + tg * 8) = *(uint4*)&os_[d * 72 + tg * 8];
        }
    }
}

// ---------------- launch ----------------
extern "C" void kernel_launch(void* const* d_in, const int* in_sizes, int n_in,
                              void* d_out, int out_size)
{
    const float* x        = (const float*)d_in[0];
    const float* qkv_w    = (const float*)d_in[2];
    const float* q_bias   = (const float*)d_in[3];
    const float* v_bias   = (const float*)d_in[4];
    const float* lscale   = (const float*)d_in[5];
    const float* cpb_w1   = (const float*)d_in[6];
    const float* cpb_b1   = (const float*)d_in[7];
    const float* cpb_w2   = (const float*)d_in[8];
    const float* proj_w   = (const float*)d_in[9];
    const float* proj_b   = (const float*)d_in[10];
    float* out = (float*)d_out;

    __half *qkv_buf, *att_buf;
    float *bq, *bp;
    unsigned *wqf, *wpf;
    cudaGetSymbolAddress((void**)&qkv_buf, g_qkvh);
    cudaGetSymbolAddress((void**)&att_buf, g_atth);
    cudaGetSymbolAddress((void**)&wqf, g_wqf);
    cudaGetSymbolAddress((void**)&wpf, g_wpf);
    cudaGetSymbolAddress((void**)&bq, g_bq);
    cudaGetSymbolAddress((void**)&bp, g_bp);

    cudaFuncSetAttribute(gemm7<0>, cudaFuncAttributeMaxDynamicSharedMemorySize, SMEM_G);
    cudaFuncSetAttribute(gemm7<1>, cudaFuncAttributeMaxDynamicSharedMemorySize, SMEM_G);

    bias_kernel<<<1, 256>>>(cpb_w1, cpb_b1, cpb_w2);
    prep_kernel<<<128, 256>>>(qkv_w, q_bias, v_bias, proj_w, proj_b);

    // QKV: fp16 window-layout output
    gemm7<0><<<dim3(MQ / 128, HW / 128, NB), 256, SMEM_G>>>(
        wqf, bq, x, nullptr, qkv_buf, 576);

    // windowed cosine attention on window-native fp16
    attn4<<<dim3(NWIN, NH, NB), 128>>>(lscale);

    // proj + bias + residual -> fp32 output
    gemm7<1><<<dim3(MP / 128, HW / 128, NB), 256, SMEM_G>>>(
        wpf, bp, att_buf, x, out, 192);
}